// round 8
// baseline (speedup 1.0000x reference)
#include <cuda_runtime.h>
#include <cuda_bf16.h>
#include <math.h>

#define B 512
#define S 64
#define KNB 8
#define D 16
#define NSTEPS 100
#define NUNITS 128

#define BS   (B*S)        // 32768
#define BSN  (BS*KNB)     // 262144
#define NDIFF (B/2)       // 256 diffusion blocks (2 batches each)

// ---- device scratch (static, allocation-free) ----
__device__ float g_urel[B * 64];
__device__ int   g_e1[BSN];
__device__ int   g_r0[BSN];
__device__ float g_ev0[BS * D];
__device__ int   g_e2[BSN * KNB];
__device__ float g_w [BSN * KNB];
__device__ float g_item[BS * D];
__device__ float g_ab[NSTEPS];
__device__ float g_omb[NSTEPS];
__device__ int   g_cnt[B];

// ---------------------------------------------------------------------------
// prep: fused k1+k2. One thread per (bs,n,k) = BSN*8 = 2.1M threads.
// Per-thread dependent chain click -> adj(e0) -> adj(e1), fully covered by TLP.
// Also: ev0 gather, urel table, alpha schedule, per-batch counters.
// ---------------------------------------------------------------------------
__global__ __launch_bounds__(256) void prep_kernel(
    const int* __restrict__ click_seq,
    const int* __restrict__ adj_ent, const int* __restrict__ adj_rel,
    const float* __restrict__ ent_emb,
    const float* __restrict__ usr_emb, const float* __restrict__ rel_emb,
    const int* __restrict__ u)
{
    int tid = threadIdx.x;
    int gt  = blockIdx.x * 256 + tid;          // [0, BSN*8)
    int bs  = gt >> 6;
    int n   = (gt >> 3) & 7;
    int k   = gt & 7;
    int bsn = (gt >> 3);
    int b   = bs >> 6;

    // hop chain (broadcast e0 across 64 lanes, e1 across 8 lanes)
    int e0 = __ldg(click_seq + bs);
    int e1 = __ldg(adj_ent + (size_t)e0 * KNB + n);
    int e2 = __ldg(adj_ent + (size_t)e1 * KNB + k);
    int r1 = __ldg(adj_rel + (size_t)e1 * KNB + k);

    // softmax weight over the 8 contiguous k-lanes
    float s = __ldg(g_urel + b * 64 + r1);     // NOTE: g_urel written below by
                                               // lower thread range of SAME launch
                                               // -> must come from urel_kernel; see below.
    // (placeholder; real value loaded after urel is available)
    (void)s;

    // --- we cannot read g_urel written in this same launch; compute the
    //     score directly instead: urel = mean_d usr[u[b]]*rel[r1]  (16 flops,
    //     rel_emb is 4 KB -> L1-resident broadcast) ---
    const float* ur = usr_emb + (size_t)__ldg(u + b) * D;
    const float4* rr = (const float4*)(rel_emb) + r1 * 4;
    float4 u0 = __ldg((const float4*)ur);
    float4 u1 = __ldg((const float4*)ur + 1);
    float4 u2 = __ldg((const float4*)ur + 2);
    float4 u3 = __ldg((const float4*)ur + 3);
    float4 r0v = __ldg(rr), r1v = __ldg(rr + 1), r2v = __ldg(rr + 2), r3v = __ldg(rr + 3);
    float sc = u0.x*r0v.x + u0.y*r0v.y + u0.z*r0v.z + u0.w*r0v.w
             + u1.x*r1v.x + u1.y*r1v.y + u1.z*r1v.z + u1.w*r1v.w
             + u2.x*r2v.x + u2.y*r2v.y + u2.z*r2v.z + u2.w*r2v.w
             + u3.x*r3v.x + u3.y*r3v.y + u3.z*r3v.z + u3.w*r3v.w;
    sc *= (1.0f / 16.0f);

    float m = sc;
    m = fmaxf(m, __shfl_xor_sync(0xffffffffu, m, 1));
    m = fmaxf(m, __shfl_xor_sync(0xffffffffu, m, 2));
    m = fmaxf(m, __shfl_xor_sync(0xffffffffu, m, 4));
    float e = expf(sc - m);
    float sum = e;
    sum += __shfl_xor_sync(0xffffffffu, sum, 1);
    sum += __shfl_xor_sync(0xffffffffu, sum, 2);
    sum += __shfl_xor_sync(0xffffffffu, sum, 4);

    g_w[gt]  = e / sum;
    g_e2[gt] = e2;

    if (k == 0) {
        g_e1[bsn] = e1;
        g_r0[bsn] = __ldg(adj_rel + (size_t)e0 * KNB + n);
    }

    // ev0: first BS*4 threads each load one float4 of ent_emb[e0']
    if (gt < BS * 4) {
        int bs2 = gt >> 2, j = gt & 3;
        int e00 = __ldg(click_seq + bs2);
        float4 v = __ldg((const float4*)ent_emb + (size_t)e00 * 4 + j);
        ((float4*)g_ev0)[bs2 * 4 + j] = v;
    }

    // urel table for k3's p0 path
    if (gt < B * 64) {
        int bb = gt >> 6, r = gt & 63;
        const float* uu = usr_emb + (size_t)__ldg(u + bb) * D;
        const float* rv = rel_emb + r * D;
        float acc = 0.f;
#pragma unroll
        for (int d = 0; d < D; d++) acc += __ldg(uu + d) * __ldg(rv + d);
        g_urel[gt] = acc * (1.0f / 16.0f);
    }
    if (gt < B) g_cnt[gt] = 0;

    // alpha schedule (block 0 only)
    if (blockIdx.x == 0) {
        __shared__ float betas[NSTEPS];
        if (tid < NSTEPS) {
            float z = -6.f + 12.f * (float)tid / 99.f;
            betas[tid] = (1.f / (1.f + expf(-z))) * (0.005f - 1e-5f) + 1e-5f;
        }
        __syncthreads();
        if (tid == 0) {
            float ap = 1.f;
            for (int i = 0; i < NSTEPS; i++) {
                ap *= (1.f - betas[i]);
                g_ab[i]  = sqrtf(ap);
                g_omb[i] = sqrtf(1.f - ap);
            }
        }
    }
}

// ---------------------------------------------------------------------------
// K3: blocks [0,NDIFF) = diffusion MLP (2 batches each);
// blocks [NDIFF, NDIFF+BS/8) = gather+aggregate for 8 (b,s) pairs;
// last-finishing block per batch runs the fusion head.
// ---------------------------------------------------------------------------
__global__ __launch_bounds__(256) void k3_kernel(
    const float* __restrict__ ent_emb,
    const float* __restrict__ agg_W, const float* __restrict__ agg_b,
    const float* __restrict__ usr_emb,
    const float* __restrict__ W1, const float* __restrict__ b1,
    const float* __restrict__ W2, const float* __restrict__ b2,
    const float* __restrict__ W3, const float* __restrict__ b3,
    const float* __restrict__ W4, const float* __restrict__ b4,
    const float* __restrict__ se1, const float* __restrict__ se2,
    const float* __restrict__ se3,
    const float* __restrict__ noise_e,
    const float* __restrict__ fc1_W, const float* __restrict__ fc1_b,
    const float* __restrict__ fc2_W, const float* __restrict__ fc2_b,
    const int* __restrict__ u, const int* __restrict__ v,
    const int* __restrict__ t,
    float* __restrict__ out)
{
    int tid = threadIdx.x;

    // ======================= diffusion path =======================
    if (blockIdx.x < NDIFF) {
        __shared__ float xs[2][16], ha[2][128], hb[2][128], p4[2][8][16];
        int bb2 = tid >> 7, tt = tid & 127;
        int b = blockIdx.x * 2 + bb2;
        int tb = __ldg(t + b);
        if (tt < 16)
            xs[bb2][tt] = __ldg(usr_emb + (size_t)__ldg(u + b) * D + tt) * __ldg(g_ab + tb)
                        + __ldg(noise_e + b * D + tt) * __ldg(g_omb + tb);
        __syncthreads();
        {
            float a = __ldg(b1 + tt) + __ldg(se1 + tb * NUNITS + tt);
#pragma unroll
            for (int d = 0; d < 16; d++)
                a = fmaf(xs[bb2][d], __ldg(W1 + d * NUNITS + tt), a);
            ha[bb2][tt] = fmaxf(a, 0.f);
        }
        __syncthreads();
        {
            float a0 = 0.f, a1 = 0.f, a2 = 0.f, a3 = 0.f;
#pragma unroll
            for (int i = 0; i < 128; i += 4) {
                a0 = fmaf(ha[bb2][i+0], __ldg(W2 + (i+0) * NUNITS + tt), a0);
                a1 = fmaf(ha[bb2][i+1], __ldg(W2 + (i+1) * NUNITS + tt), a1);
                a2 = fmaf(ha[bb2][i+2], __ldg(W2 + (i+2) * NUNITS + tt), a2);
                a3 = fmaf(ha[bb2][i+3], __ldg(W2 + (i+3) * NUNITS + tt), a3);
            }
            float a = __ldg(b2 + tt) + __ldg(se2 + tb * NUNITS + tt)
                    + ((a0 + a1) + (a2 + a3));
            hb[bb2][tt] = fmaxf(a, 0.f);
        }
        __syncthreads();
        {
            float a0 = 0.f, a1 = 0.f, a2 = 0.f, a3 = 0.f;
#pragma unroll
            for (int i = 0; i < 128; i += 4) {
                a0 = fmaf(hb[bb2][i+0], __ldg(W3 + (i+0) * NUNITS + tt), a0);
                a1 = fmaf(hb[bb2][i+1], __ldg(W3 + (i+1) * NUNITS + tt), a1);
                a2 = fmaf(hb[bb2][i+2], __ldg(W3 + (i+2) * NUNITS + tt), a2);
                a3 = fmaf(hb[bb2][i+3], __ldg(W3 + (i+3) * NUNITS + tt), a3);
            }
            float a = __ldg(b3 + tt) + __ldg(se3 + tb * NUNITS + tt)
                    + ((a0 + a1) + (a2 + a3));
            ha[bb2][tt] = fmaxf(a, 0.f);
        }
        __syncthreads();
        {
            int g = tt >> 4, d = tt & 15;
            float a = 0.f;
#pragma unroll
            for (int i = 0; i < 16; i++)
                a = fmaf(ha[bb2][g * 16 + i], __ldg(W4 + (g * 16 + i) * D + d), a);
            p4[bb2][g][d] = a;
        }
        __syncthreads();
        if (tt < 16) {
            float a = __ldg(b4 + tt);
#pragma unroll
            for (int g = 0; g < 8; g++) a += p4[bb2][g][tt];
            out[b * (1 + D) + 1 + tt] = a;
        }
        return;
    }

    // ======================= gather path =======================
    __shared__ float Wm[256], bb[16];
    __shared__ float tmp1s[8][8][17];
    __shared__ float ev1s[8][8][17];
    __shared__ float out1s[8][8][17];
    __shared__ float ev0s[8][16];
    __shared__ float p0s[8][8];
    __shared__ float t0s[8][17];
    __shared__ float tfs[8][17];
    __shared__ int   headflag;

    int gb  = blockIdx.x - NDIFF;
    int bsl = tid >> 5, n = (tid >> 2) & 7, q = tid & 3;
    int bs  = gb * 8 + bsl;
    int bsn = bs * KNB + n;
    int b   = bs >> 6;
    int bq  = (gb * 8) >> 6;

    Wm[tid] = __ldg(agg_W + tid);
    if (tid < 16) bb[tid] = __ldg(agg_b + tid);

    int4   ea = __ldg((const int4*)g_e2 + bsn * 2);
    int4   eb = __ldg((const int4*)g_e2 + bsn * 2 + 1);
    float4 wa = __ldg((const float4*)g_w + bsn * 2);
    float4 wb = __ldg((const float4*)g_w + bsn * 2 + 1);
    int e1 = __ldg(g_e1 + bsn);

    const float4* E = (const float4*)ent_emb;
    float4 v0 = __ldg(E + (size_t)ea.x * 4 + q);
    float4 v1 = __ldg(E + (size_t)ea.y * 4 + q);
    float4 v2 = __ldg(E + (size_t)ea.z * 4 + q);
    float4 v3 = __ldg(E + (size_t)ea.w * 4 + q);
    float4 v4 = __ldg(E + (size_t)eb.x * 4 + q);
    float4 v5 = __ldg(E + (size_t)eb.y * 4 + q);
    float4 v6 = __ldg(E + (size_t)eb.z * 4 + q);
    float4 v7 = __ldg(E + (size_t)eb.w * 4 + q);
    float4 e1v = __ldg(E + (size_t)e1 * 4 + q);

    float4 acc;
    acc.x = wa.x*v0.x + wa.y*v1.x + wa.z*v2.x + wa.w*v3.x
          + wb.x*v4.x + wb.y*v5.x + wb.z*v6.x + wb.w*v7.x;
    acc.y = wa.x*v0.y + wa.y*v1.y + wa.z*v2.y + wa.w*v3.y
          + wb.x*v4.y + wb.y*v5.y + wb.z*v6.y + wb.w*v7.y;
    acc.z = wa.x*v0.z + wa.y*v1.z + wa.z*v2.z + wa.w*v3.z
          + wb.x*v4.z + wb.y*v5.z + wb.z*v6.z + wb.w*v7.z;
    acc.w = wa.x*v0.w + wa.y*v1.w + wa.z*v2.w + wa.w*v3.w
          + wb.x*v4.w + wb.y*v5.w + wb.z*v6.w + wb.w*v7.w;

    int qq = q * 4;
    tmp1s[bsl][n][qq+0] = e1v.x + acc.x;
    tmp1s[bsl][n][qq+1] = e1v.y + acc.y;
    tmp1s[bsl][n][qq+2] = e1v.z + acc.z;
    tmp1s[bsl][n][qq+3] = e1v.w + acc.w;
    ev1s[bsl][n][qq+0] = e1v.x;
    ev1s[bsl][n][qq+1] = e1v.y;
    ev1s[bsl][n][qq+2] = e1v.z;
    ev1s[bsl][n][qq+3] = e1v.w;

    if (tid < 128) {
        int bl = tid >> 4, d = tid & 15;
        ev0s[bl][d] = __ldg(g_ev0 + (size_t)(gb * 8 + bl) * 16 + d);
    }

    {
        int r0 = __ldg(g_r0 + bsn);
        float s = __ldg(g_urel + b * 64 + r0);
        float m = s;
        m = fmaxf(m, __shfl_xor_sync(0xffffffffu, m, 4));
        m = fmaxf(m, __shfl_xor_sync(0xffffffffu, m, 8));
        m = fmaxf(m, __shfl_xor_sync(0xffffffffu, m, 16));
        float e = expf(s - m);
        float sum = e;
        sum += __shfl_xor_sync(0xffffffffu, sum, 4);
        sum += __shfl_xor_sync(0xffffffffu, sum, 8);
        sum += __shfl_xor_sync(0xffffffffu, sum, 16);
        if (q == 0) p0s[bsl][n] = e / sum;
    }
    __syncthreads();

#pragma unroll
    for (int j = 0; j < 4; j++) {
        int o = tid + 256 * j;
        int bl = o >> 7, n2 = (o >> 4) & 7, dp = o & 15;
        float a = bb[dp];
#pragma unroll
        for (int d = 0; d < 16; d++)
            a = fmaf(tmp1s[bl][n2][d], Wm[d * 16 + dp], a);
        out1s[bl][n2][dp] = 1.f / (1.f + expf(-a));
    }
    if (tid < 128) {
        int bl = tid >> 4, d = tid & 15;
        float t0 = ev0s[bl][d];
#pragma unroll
        for (int k = 0; k < 8; k++)
            t0 = fmaf(p0s[bl][k], ev1s[bl][k][d], t0);
        t0s[bl][d] = t0;
    }
    __syncthreads();

    if (tid < 128) {
        int bl = tid >> 4, d = tid & 15;
        float a = bb[d];
#pragma unroll
        for (int d2 = 0; d2 < 16; d2++)
            a = fmaf(t0s[bl][d2], Wm[d2 * 16 + d], a);
        float o0 = 1.f / (1.f + expf(-a));
        float tf = o0;
#pragma unroll
        for (int k = 0; k < 8; k++)
            tf = fmaf(p0s[bl][k], out1s[bl][k][d], tf);
        tfs[bl][d] = tf;
    }
    __syncthreads();

    if (tid < 128) {
        int bl = tid >> 4, d = tid & 15;
        float a = bb[d];
#pragma unroll
        for (int d2 = 0; d2 < 16; d2++)
            a = fmaf(tfs[bl][d2], Wm[d2 * 16 + d], a);
        g_item[(size_t)(gb * 8 + bl) * 16 + d] = fmaxf(tanhf(a), 0.f);
    }

    // -------- last-block-per-batch fusion head --------
    if (tid == 0) {
        __threadfence();
        int old = atomicAdd(&g_cnt[bq], 1);
        headflag = (old == 7);
    }
    __syncthreads();
    if (!headflag) return;
    __threadfence();

    __shared__ float ps[8][16], pm[8][16], fus[32], hh[64];
    if (tid < 128) {
        int d = tid & 15, sc = tid >> 4;
        float s = 0.f, m = -1e30f;
#pragma unroll
        for (int j = 0; j < 8; j++) {
            float vv = g_item[((size_t)bq * S + sc * 8 + j) * D + d];
            s += vv;
            m = fmaxf(m, vv);
        }
        ps[sc][d] = s;
        pm[sc][d] = m;
    }
    __syncthreads();
    if (tid < 16) {
        float s = 0.f, m = -1e30f;
#pragma unroll
        for (int c = 0; c < 8; c++) { s += ps[c][tid]; m = fmaxf(m, pm[c][tid]); }
        fus[tid]      = fmaxf(s, 0.f);
        fus[16 + tid] = fmaxf(m, 0.f);
    }
    __syncthreads();
    if (tid < 64) {
        float a = __ldg(fc1_b + tid);
#pragma unroll
        for (int i = 0; i < 32; i++)
            a = fmaf(fus[i], __ldg(fc1_W + i * 64 + tid), a);
        hh[tid] = fmaxf(a, 0.f);
    }
    __syncthreads();
    if (tid < 16) {
        float a = __ldg(fc2_b + tid);
#pragma unroll
        for (int i = 0; i < 64; i++)
            a = fmaf(hh[i], __ldg(fc2_W + i * D + tid), a);
        float f = fmaxf(a, 0.f);
        float p = f * __ldg(ent_emb + (size_t)__ldg(v + bq) * D + tid);
        p += __shfl_xor_sync(0xffffu, p, 8);
        p += __shfl_xor_sync(0xffffu, p, 4);
        p += __shfl_xor_sync(0xffffu, p, 2);
        p += __shfl_xor_sync(0xffffu, p, 1);
        if (tid == 0)
            out[bq * (1 + D)] = 1.f / (1.f + expf(-p));
    }
}

// ---------------------------------------------------------------------------
extern "C" void kernel_launch(void* const* d_in, const int* in_sizes, int n_in,
                              void* d_out, int out_size)
{
    const float* usr_emb  = (const float*)d_in[0];
    const float* ent_emb  = (const float*)d_in[1];
    const float* rel_emb  = (const float*)d_in[2];
    const float* agg_W    = (const float*)d_in[3];
    const float* agg_b    = (const float*)d_in[4];
    const float* fc1_W    = (const float*)d_in[5];
    const float* fc1_b    = (const float*)d_in[6];
    const float* fc2_W    = (const float*)d_in[7];
    const float* fc2_b    = (const float*)d_in[8];
    const float* mlp_W1   = (const float*)d_in[9];
    const float* mlp_b1   = (const float*)d_in[10];
    const float* mlp_W2   = (const float*)d_in[11];
    const float* mlp_b2   = (const float*)d_in[12];
    const float* mlp_W3   = (const float*)d_in[13];
    const float* mlp_b3   = (const float*)d_in[14];
    const float* mlp_W4   = (const float*)d_in[15];
    const float* mlp_b4   = (const float*)d_in[16];
    const float* se1      = (const float*)d_in[17];
    const float* se2      = (const float*)d_in[18];
    const float* se3      = (const float*)d_in[19];
    const float* noise_e  = (const float*)d_in[20];
    const int*   u        = (const int*)d_in[21];
    const int*   v        = (const int*)d_in[22];
    const int*   click    = (const int*)d_in[23];
    const int*   adj_ent  = (const int*)d_in[24];
    const int*   adj_rel  = (const int*)d_in[25];
    const int*   t        = (const int*)d_in[26];
    float* out = (float*)d_out;

    prep_kernel<<<(BSN * KNB) / 256, 256>>>(click, adj_ent, adj_rel, ent_emb,
                                            usr_emb, rel_emb, u);
    k3_kernel<<<NDIFF + BS / 8, 256>>>(ent_emb, agg_W, agg_b, usr_emb,
                                       mlp_W1, mlp_b1, mlp_W2, mlp_b2,
                                       mlp_W3, mlp_b3, mlp_W4, mlp_b4,
                                       se1, se2, se3, noise_e,
                                       fc1_W, fc1_b, fc2_W, fc2_b,
                                       u, v, t, out);
}

// round 9
// speedup vs baseline: 1.4824x; 1.4824x over previous
#include <cuda_runtime.h>
#include <cuda_bf16.h>
#include <math.h>

#define B 512
#define S 64
#define KNB 8
#define D 16
#define NSTEPS 100
#define NUNITS 128

#define BS    (B*S)       // 32768
#define NDIFF (B/2)       // 256 diffusion blocks (2 batches each)
#define NGATH (BS/8)      // 4096 gather blocks (8 (b,s) each)

// ---- device scratch (static, allocation-free) ----
__device__ float g_item[BS * D];
__device__ unsigned int g_cnt[B];   // monotonic; head = (old & 7) == 7

// ---------------------------------------------------------------------------
// Single fused kernel.
//   blocks [0, NDIFF)            : diffusion MLP, 2 batches each
//   blocks [NDIFF, NDIFF+NGATH)  : full KGCN chain for 8 (b,s); last block
//                                  per batch runs the fusion head.
// ---------------------------------------------------------------------------
__global__ __launch_bounds__(256) void fused_kernel(
    const float* __restrict__ ent_emb,
    const float* __restrict__ rel_emb,
    const float* __restrict__ agg_W, const float* __restrict__ agg_b,
    const float* __restrict__ usr_emb,
    const float* __restrict__ W1, const float* __restrict__ b1,
    const float* __restrict__ W2, const float* __restrict__ b2,
    const float* __restrict__ W3, const float* __restrict__ b3,
    const float* __restrict__ W4, const float* __restrict__ b4,
    const float* __restrict__ se1, const float* __restrict__ se2,
    const float* __restrict__ se3,
    const float* __restrict__ noise_e,
    const float* __restrict__ fc1_W, const float* __restrict__ fc1_b,
    const float* __restrict__ fc2_W, const float* __restrict__ fc2_b,
    const int* __restrict__ u, const int* __restrict__ v,
    const int* __restrict__ t,
    const int* __restrict__ click_seq,
    const int* __restrict__ adj_ent, const int* __restrict__ adj_rel,
    float* __restrict__ out)
{
    int tid = threadIdx.x;

    // ======================= diffusion path =======================
    if (blockIdx.x < NDIFF) {
        __shared__ float red[256];
        __shared__ float xs[2][16], ha[2][128], hb[2][128], p4[2][8][16];
        int bb2 = tid >> 7, tt = tid & 127;
        int b = blockIdx.x * 2 + bb2;
        int tb = __ldg(t + b);

        // alpha-bar via parallel log1p sum (exact enough: rel err ~1e-7)
        float lg = 0.f;
        if (tt < NSTEPS && tt <= tb) {
            float z = -6.f + 12.f * (float)tt / 99.f;
            float beta = (1.f / (1.f + expf(-z))) * (0.005f - 1e-5f) + 1e-5f;
            lg = log1pf(-beta);
        }
        red[tid] = lg;
        __syncthreads();
#pragma unroll
        for (int st = 64; st > 0; st >>= 1) {
            if (tt < st) red[bb2 * 128 + tt] += red[bb2 * 128 + tt + st];
            __syncthreads();
        }
        float ap  = expf(red[bb2 * 128]);
        float ab  = sqrtf(ap);
        float omb = sqrtf(1.f - ap);

        if (tt < 16)
            xs[bb2][tt] = __ldg(usr_emb + (size_t)__ldg(u + b) * D + tt) * ab
                        + __ldg(noise_e + b * D + tt) * omb;
        __syncthreads();
        {
            float a = __ldg(b1 + tt) + __ldg(se1 + tb * NUNITS + tt);
#pragma unroll
            for (int d = 0; d < 16; d++)
                a = fmaf(xs[bb2][d], __ldg(W1 + d * NUNITS + tt), a);
            ha[bb2][tt] = fmaxf(a, 0.f);
        }
        __syncthreads();
        {
            float a0 = 0.f, a1 = 0.f, a2 = 0.f, a3 = 0.f;
#pragma unroll
            for (int i = 0; i < 128; i += 4) {
                a0 = fmaf(ha[bb2][i+0], __ldg(W2 + (i+0) * NUNITS + tt), a0);
                a1 = fmaf(ha[bb2][i+1], __ldg(W2 + (i+1) * NUNITS + tt), a1);
                a2 = fmaf(ha[bb2][i+2], __ldg(W2 + (i+2) * NUNITS + tt), a2);
                a3 = fmaf(ha[bb2][i+3], __ldg(W2 + (i+3) * NUNITS + tt), a3);
            }
            float a = __ldg(b2 + tt) + __ldg(se2 + tb * NUNITS + tt)
                    + ((a0 + a1) + (a2 + a3));
            hb[bb2][tt] = fmaxf(a, 0.f);
        }
        __syncthreads();
        {
            float a0 = 0.f, a1 = 0.f, a2 = 0.f, a3 = 0.f;
#pragma unroll
            for (int i = 0; i < 128; i += 4) {
                a0 = fmaf(hb[bb2][i+0], __ldg(W3 + (i+0) * NUNITS + tt), a0);
                a1 = fmaf(hb[bb2][i+1], __ldg(W3 + (i+1) * NUNITS + tt), a1);
                a2 = fmaf(hb[bb2][i+2], __ldg(W3 + (i+2) * NUNITS + tt), a2);
                a3 = fmaf(hb[bb2][i+3], __ldg(W3 + (i+3) * NUNITS + tt), a3);
            }
            float a = __ldg(b3 + tt) + __ldg(se3 + tb * NUNITS + tt)
                    + ((a0 + a1) + (a2 + a3));
            ha[bb2][tt] = fmaxf(a, 0.f);
        }
        __syncthreads();
        {
            int g = tt >> 4, d = tt & 15;
            float a = 0.f;
#pragma unroll
            for (int i = 0; i < 16; i++)
                a = fmaf(ha[bb2][g * 16 + i], __ldg(W4 + (g * 16 + i) * D + d), a);
            p4[bb2][g][d] = a;
        }
        __syncthreads();
        if (tt < 16) {
            float a = __ldg(b4 + tt);
#pragma unroll
            for (int g = 0; g < 8; g++) a += p4[bb2][g][tt];
            out[b * (1 + D) + 1 + tt] = a;
        }
        return;
    }

    // ======================= gather path =======================
    __shared__ float urel_s[64];
    __shared__ float Wm[256], bbias[16];
    __shared__ float tmp1s[8][8][17];
    __shared__ float ev1s[8][8][17];
    __shared__ float out1s[8][8][17];
    __shared__ float ev0s[8][16];
    __shared__ float p0s[8][8];
    __shared__ float t0s[8][17];
    __shared__ float tfs[8][17];
    __shared__ int   headflag;

    int gb  = blockIdx.x - NDIFF;
    int bsl = tid >> 5, n = (tid >> 2) & 7, q = tid & 3;
    int bs  = gb * 8 + bsl;
    int bq  = bs >> 6;                 // same batch for all 8 bs in block

    Wm[tid] = __ldg(agg_W + tid);
    if (tid < 16) bbias[tid] = __ldg(agg_b + tid);

    // per-block urel table: urel[r] = mean_d usr[u[bq]][d]*rel[r][d]
    if (tid < 64) {
        const float4* uu = (const float4*)usr_emb + (size_t)__ldg(u + bq) * 4;
        const float4* rv = (const float4*)rel_emb + tid * 4;
        float4 a0 = __ldg(uu), a1 = __ldg(uu + 1), a2 = __ldg(uu + 2), a3 = __ldg(uu + 3);
        float4 c0 = __ldg(rv), c1 = __ldg(rv + 1), c2 = __ldg(rv + 2), c3 = __ldg(rv + 3);
        float sd = a0.x*c0.x + a0.y*c0.y + a0.z*c0.z + a0.w*c0.w
                 + a1.x*c1.x + a1.y*c1.y + a1.z*c1.z + a1.w*c1.w
                 + a2.x*c2.x + a2.y*c2.y + a2.z*c2.z + a2.w*c2.w
                 + a3.x*c3.x + a3.y*c3.y + a3.z*c3.z + a3.w*c3.w;
        urel_s[tid] = sd * (1.0f / 16.0f);
    }

    // -------- index chain (per warp = one bs) --------
    const float4* E = (const float4*)ent_emb;
    int e0 = __ldg(click_seq + bs);                                 // broadcast
    int e1 = __ldg(adj_ent + (size_t)e0 * KNB + n);                 // 8 distinct
    int r0 = __ldg(adj_rel + (size_t)e0 * KNB + n);
    int2 e2p = __ldg((const int2*)(adj_ent + (size_t)e1 * KNB) + q); // 32B/row
    int2 r1p = __ldg((const int2*)(adj_rel + (size_t)e1 * KNB) + q);

    // ev1 + ev0 (independent loads, overlap chain)
    float4 e1v = __ldg(E + (size_t)e1 * 4 + q);
    if (n == 0) {
        float4 v = __ldg(E + (size_t)e0 * 4 + q);
        ev0s[bsl][q*4+0] = v.x; ev0s[bsl][q*4+1] = v.y;
        ev0s[bsl][q*4+2] = v.z; ev0s[bsl][q*4+3] = v.w;
    }

    __syncthreads();   // urel_s ready

    // -------- p1 softmax: 8 scores held 2-per-lane across 4 q-lanes --------
    float s0 = urel_s[r1p.x], s1 = urel_s[r1p.y];
    float m = fmaxf(s0, s1);
    m = fmaxf(m, __shfl_xor_sync(0xffffffffu, m, 1));
    m = fmaxf(m, __shfl_xor_sync(0xffffffffu, m, 2));
    float ew0 = expf(s0 - m), ew1 = expf(s1 - m);
    float sum = ew0 + ew1;
    sum += __shfl_xor_sync(0xffffffffu, sum, 1);
    sum += __shfl_xor_sync(0xffffffffu, sum, 2);
    float inv = 1.f / sum;
    float w0 = ew0 * inv, w1 = ew1 * inv;

    // distribute all 8 (e2, w) across the 4-lane group
    int lb = (tid & 31) & ~3;   // lane base within warp
    int eA0 = __shfl_sync(0xffffffffu, e2p.x, lb+0), eB0 = __shfl_sync(0xffffffffu, e2p.y, lb+0);
    int eA1 = __shfl_sync(0xffffffffu, e2p.x, lb+1), eB1 = __shfl_sync(0xffffffffu, e2p.y, lb+1);
    int eA2 = __shfl_sync(0xffffffffu, e2p.x, lb+2), eB2 = __shfl_sync(0xffffffffu, e2p.y, lb+2);
    int eA3 = __shfl_sync(0xffffffffu, e2p.x, lb+3), eB3 = __shfl_sync(0xffffffffu, e2p.y, lb+3);
    float wA0 = __shfl_sync(0xffffffffu, w0, lb+0), wB0 = __shfl_sync(0xffffffffu, w1, lb+0);
    float wA1 = __shfl_sync(0xffffffffu, w0, lb+1), wB1 = __shfl_sync(0xffffffffu, w1, lb+1);
    float wA2 = __shfl_sync(0xffffffffu, w0, lb+2), wB2 = __shfl_sync(0xffffffffu, w1, lb+2);
    float wA3 = __shfl_sync(0xffffffffu, w0, lb+3), wB3 = __shfl_sync(0xffffffffu, w1, lb+3);

    // -------- the hot random gather: 8 independent float4 loads --------
    float4 v0 = __ldg(E + (size_t)eA0 * 4 + q);
    float4 v1 = __ldg(E + (size_t)eB0 * 4 + q);
    float4 v2 = __ldg(E + (size_t)eA1 * 4 + q);
    float4 v3 = __ldg(E + (size_t)eB1 * 4 + q);
    float4 v4 = __ldg(E + (size_t)eA2 * 4 + q);
    float4 v5 = __ldg(E + (size_t)eB2 * 4 + q);
    float4 v6 = __ldg(E + (size_t)eA3 * 4 + q);
    float4 v7 = __ldg(E + (size_t)eB3 * 4 + q);

    float4 acc;
    acc.x = wA0*v0.x + wB0*v1.x + wA1*v2.x + wB1*v3.x
          + wA2*v4.x + wB2*v5.x + wA3*v6.x + wB3*v7.x;
    acc.y = wA0*v0.y + wB0*v1.y + wA1*v2.y + wB1*v3.y
          + wA2*v4.y + wB2*v5.y + wA3*v6.y + wB3*v7.y;
    acc.z = wA0*v0.z + wB0*v1.z + wA1*v2.z + wB1*v3.z
          + wA2*v4.z + wB2*v5.z + wA3*v6.z + wB3*v7.z;
    acc.w = wA0*v0.w + wB0*v1.w + wA1*v2.w + wB1*v3.w
          + wA2*v4.w + wB2*v5.w + wA3*v6.w + wB3*v7.w;

    int qq = q * 4;
    tmp1s[bsl][n][qq+0] = e1v.x + acc.x;
    tmp1s[bsl][n][qq+1] = e1v.y + acc.y;
    tmp1s[bsl][n][qq+2] = e1v.z + acc.z;
    tmp1s[bsl][n][qq+3] = e1v.w + acc.w;
    ev1s[bsl][n][qq+0] = e1v.x;
    ev1s[bsl][n][qq+1] = e1v.y;
    ev1s[bsl][n][qq+2] = e1v.z;
    ev1s[bsl][n][qq+3] = e1v.w;

    // -------- p0 softmax (over n within warp; q-redundant) --------
    {
        float s = urel_s[r0];
        float mm = s;
        mm = fmaxf(mm, __shfl_xor_sync(0xffffffffu, mm, 4));
        mm = fmaxf(mm, __shfl_xor_sync(0xffffffffu, mm, 8));
        mm = fmaxf(mm, __shfl_xor_sync(0xffffffffu, mm, 16));
        float e = expf(s - mm);
        float su = e;
        su += __shfl_xor_sync(0xffffffffu, su, 4);
        su += __shfl_xor_sync(0xffffffffu, su, 8);
        su += __shfl_xor_sync(0xffffffffu, su, 16);
        if (q == 0) p0s[bsl][n] = e / su;
    }
    __syncthreads();

    // -------- hop1 linear + sigmoid; t0 partial --------
#pragma unroll
    for (int j = 0; j < 4; j++) {
        int o = tid + 256 * j;
        int bl = o >> 7, n2 = (o >> 4) & 7, dp = o & 15;
        float a = bbias[dp];
#pragma unroll
        for (int d = 0; d < 16; d++)
            a = fmaf(tmp1s[bl][n2][d], Wm[d * 16 + dp], a);
        out1s[bl][n2][dp] = 1.f / (1.f + expf(-a));
    }
    if (tid < 128) {
        int bl = tid >> 4, d = tid & 15;
        float t0 = ev0s[bl][d];
#pragma unroll
        for (int k = 0; k < 8; k++)
            t0 = fmaf(p0s[bl][k], ev1s[bl][k][d], t0);
        t0s[bl][d] = t0;
    }
    __syncthreads();

    if (tid < 128) {
        int bl = tid >> 4, d = tid & 15;
        float a = bbias[d];
#pragma unroll
        for (int d2 = 0; d2 < 16; d2++)
            a = fmaf(t0s[bl][d2], Wm[d2 * 16 + d], a);
        float o0 = 1.f / (1.f + expf(-a));
        float tf = o0;
#pragma unroll
        for (int k = 0; k < 8; k++)
            tf = fmaf(p0s[bl][k], out1s[bl][k][d], tf);
        tfs[bl][d] = tf;
    }
    __syncthreads();

    if (tid < 128) {
        int bl = tid >> 4, d = tid & 15;
        float a = bbias[d];
#pragma unroll
        for (int d2 = 0; d2 < 16; d2++)
            a = fmaf(tfs[bl][d2], Wm[d2 * 16 + d], a);
        g_item[(size_t)(gb * 8 + bl) * 16 + d] = fmaxf(tanhf(a), 0.f);
    }

    // -------- last-block-per-batch fusion head (mod-8 counter, no reset) ----
    if (tid == 0) {
        __threadfence();
        unsigned int old = atomicAdd(&g_cnt[bq], 1u);
        headflag = ((old & 7u) == 7u);
    }
    __syncthreads();
    if (!headflag) return;
    __threadfence();

    __shared__ float ps[8][16], pm[8][16], fus[32], hh[64];
    if (tid < 128) {
        int d = tid & 15, sc = tid >> 4;
        float s = 0.f, mmx = -1e30f;
#pragma unroll
        for (int j = 0; j < 8; j++) {
            float vv = g_item[((size_t)bq * S + sc * 8 + j) * D + d];
            s += vv;
            mmx = fmaxf(mmx, vv);
        }
        ps[sc][d] = s;
        pm[sc][d] = mmx;
    }
    __syncthreads();
    if (tid < 16) {
        float s = 0.f, mmx = -1e30f;
#pragma unroll
        for (int c = 0; c < 8; c++) { s += ps[c][tid]; mmx = fmaxf(mmx, pm[c][tid]); }
        fus[tid]      = fmaxf(s, 0.f);
        fus[16 + tid] = fmaxf(mmx, 0.f);
    }
    __syncthreads();
    if (tid < 64) {
        float a = __ldg(fc1_b + tid);
#pragma unroll
        for (int i = 0; i < 32; i++)
            a = fmaf(fus[i], __ldg(fc1_W + i * 64 + tid), a);
        hh[tid] = fmaxf(a, 0.f);
    }
    __syncthreads();
    if (tid < 16) {
        float a = __ldg(fc2_b + tid);
#pragma unroll
        for (int i = 0; i < 64; i++)
            a = fmaf(hh[i], __ldg(fc2_W + i * D + tid), a);
        float f = fmaxf(a, 0.f);
        float p = f * __ldg(ent_emb + (size_t)__ldg(v + bq) * D + tid);
        p += __shfl_xor_sync(0xffffu, p, 8);
        p += __shfl_xor_sync(0xffffu, p, 4);
        p += __shfl_xor_sync(0xffffu, p, 2);
        p += __shfl_xor_sync(0xffffu, p, 1);
        if (tid == 0)
            out[bq * (1 + D)] = 1.f / (1.f + expf(-p));
    }
}

// ---------------------------------------------------------------------------
extern "C" void kernel_launch(void* const* d_in, const int* in_sizes, int n_in,
                              void* d_out, int out_size)
{
    const float* usr_emb  = (const float*)d_in[0];
    const float* ent_emb  = (const float*)d_in[1];
    const float* rel_emb  = (const float*)d_in[2];
    const float* agg_W    = (const float*)d_in[3];
    const float* agg_b    = (const float*)d_in[4];
    const float* fc1_W    = (const float*)d_in[5];
    const float* fc1_b    = (const float*)d_in[6];
    const float* fc2_W    = (const float*)d_in[7];
    const float* fc2_b    = (const float*)d_in[8];
    const float* mlp_W1   = (const float*)d_in[9];
    const float* mlp_b1   = (const float*)d_in[10];
    const float* mlp_W2   = (const float*)d_in[11];
    const float* mlp_b2   = (const float*)d_in[12];
    const float* mlp_W3   = (const float*)d_in[13];
    const float* mlp_b3   = (const float*)d_in[14];
    const float* mlp_W4   = (const float*)d_in[15];
    const float* mlp_b4   = (const float*)d_in[16];
    const float* se1      = (const float*)d_in[17];
    const float* se2      = (const float*)d_in[18];
    const float* se3      = (const float*)d_in[19];
    const float* noise_e  = (const float*)d_in[20];
    const int*   u        = (const int*)d_in[21];
    const int*   v        = (const int*)d_in[22];
    const int*   click    = (const int*)d_in[23];
    const int*   adj_ent  = (const int*)d_in[24];
    const int*   adj_rel  = (const int*)d_in[25];
    const int*   t        = (const int*)d_in[26];
    float* out = (float*)d_out;

    fused_kernel<<<NDIFF + NGATH, 256>>>(ent_emb, rel_emb, agg_W, agg_b, usr_emb,
                                         mlp_W1, mlp_b1, mlp_W2, mlp_b2,
                                         mlp_W3, mlp_b3, mlp_W4, mlp_b4,
                                         se1, se2, se3, noise_e,
                                         fc1_W, fc1_b, fc2_W, fc2_b,
                                         u, v, t, click, adj_ent, adj_rel, out);
}

// round 10
// speedup vs baseline: 1.5053x; 1.0155x over previous
#include <cuda_runtime.h>
#include <cuda_bf16.h>
#include <math.h>

#define B 512
#define S 64
#define KNB 8
#define D 16
#define NSTEPS 100
#define NUNITS 128

#define BS    (B*S)       // 32768
#define NDIFF (B)         // 512 diffusion blocks (1 batch each)
#define NGATH (BS/4)      // 8192 gather blocks (4 (b,s) each)

// ---- device scratch (static, allocation-free) ----
__device__ float g_item[BS * D];
__device__ unsigned int g_cnt[B];   // monotonic; head = (old & 15) == 15

__device__ __forceinline__ float fsigmoid(float a) {
    return __fdividef(1.f, 1.f + __expf(-a));
}

// ---------------------------------------------------------------------------
// Single fused kernel, 128-thread blocks.
//   blocks [0, NDIFF)            : diffusion MLP, 1 batch each
//   blocks [NDIFF, NDIFF+NGATH)  : full KGCN chain for 4 (b,s); 16th-arriving
//                                  block per batch runs the fusion head.
// ---------------------------------------------------------------------------
__global__ __launch_bounds__(128) void fused_kernel(
    const float* __restrict__ ent_emb,
    const float* __restrict__ rel_emb,
    const float* __restrict__ agg_W, const float* __restrict__ agg_b,
    const float* __restrict__ usr_emb,
    const float* __restrict__ W1, const float* __restrict__ b1,
    const float* __restrict__ W2, const float* __restrict__ b2,
    const float* __restrict__ W3, const float* __restrict__ b3,
    const float* __restrict__ W4, const float* __restrict__ b4,
    const float* __restrict__ se1, const float* __restrict__ se2,
    const float* __restrict__ se3,
    const float* __restrict__ noise_e,
    const float* __restrict__ fc1_W, const float* __restrict__ fc1_b,
    const float* __restrict__ fc2_W, const float* __restrict__ fc2_b,
    const int* __restrict__ u, const int* __restrict__ v,
    const int* __restrict__ t,
    const int* __restrict__ click_seq,
    const int* __restrict__ adj_ent, const int* __restrict__ adj_rel,
    float* __restrict__ out)
{
    int tid = threadIdx.x;

    // ======================= diffusion path =======================
    if (blockIdx.x < NDIFF) {
        __shared__ float red[128];
        __shared__ float xs[16], ha[128], hb[128], p4[8][16];
        int b = blockIdx.x;
        int tb = __ldg(t + b);

        // alpha-bar via parallel log1p sum
        float lg = 0.f;
        if (tid < NSTEPS && tid <= tb) {
            float z = -6.f + 12.f * (float)tid / 99.f;
            float beta = fsigmoid(z) * (0.005f - 1e-5f) + 1e-5f;
            lg = log1pf(-beta);
        }
        red[tid] = lg;
        __syncthreads();
#pragma unroll
        for (int st = 64; st > 0; st >>= 1) {
            if (tid < st) red[tid] += red[tid + st];
            __syncthreads();
        }
        float ap  = __expf(red[0]);
        float ab  = sqrtf(ap);
        float omb = sqrtf(1.f - ap);

        if (tid < 16)
            xs[tid] = __ldg(usr_emb + (size_t)__ldg(u + b) * D + tid) * ab
                    + __ldg(noise_e + b * D + tid) * omb;
        __syncthreads();
        {
            float a = __ldg(b1 + tid) + __ldg(se1 + tb * NUNITS + tid);
#pragma unroll
            for (int d = 0; d < 16; d++)
                a = fmaf(xs[d], __ldg(W1 + d * NUNITS + tid), a);
            ha[tid] = fmaxf(a, 0.f);
        }
        __syncthreads();
        {
            float a0 = 0.f, a1 = 0.f, a2 = 0.f, a3 = 0.f;
#pragma unroll
            for (int i = 0; i < 128; i += 4) {
                a0 = fmaf(ha[i+0], __ldg(W2 + (i+0) * NUNITS + tid), a0);
                a1 = fmaf(ha[i+1], __ldg(W2 + (i+1) * NUNITS + tid), a1);
                a2 = fmaf(ha[i+2], __ldg(W2 + (i+2) * NUNITS + tid), a2);
                a3 = fmaf(ha[i+3], __ldg(W2 + (i+3) * NUNITS + tid), a3);
            }
            float a = __ldg(b2 + tid) + __ldg(se2 + tb * NUNITS + tid)
                    + ((a0 + a1) + (a2 + a3));
            hb[tid] = fmaxf(a, 0.f);
        }
        __syncthreads();
        {
            float a0 = 0.f, a1 = 0.f, a2 = 0.f, a3 = 0.f;
#pragma unroll
            for (int i = 0; i < 128; i += 4) {
                a0 = fmaf(hb[i+0], __ldg(W3 + (i+0) * NUNITS + tid), a0);
                a1 = fmaf(hb[i+1], __ldg(W3 + (i+1) * NUNITS + tid), a1);
                a2 = fmaf(hb[i+2], __ldg(W3 + (i+2) * NUNITS + tid), a2);
                a3 = fmaf(hb[i+3], __ldg(W3 + (i+3) * NUNITS + tid), a3);
            }
            float a = __ldg(b3 + tid) + __ldg(se3 + tb * NUNITS + tid)
                    + ((a0 + a1) + (a2 + a3));
            ha[tid] = fmaxf(a, 0.f);
        }
        __syncthreads();
        {
            int g = tid >> 4, d = tid & 15;
            float a = 0.f;
#pragma unroll
            for (int i = 0; i < 16; i++)
                a = fmaf(ha[g * 16 + i], __ldg(W4 + (g * 16 + i) * D + d), a);
            p4[g][d] = a;
        }
        __syncthreads();
        if (tid < 16) {
            float a = __ldg(b4 + tid);
#pragma unroll
            for (int g = 0; g < 8; g++) a += p4[g][tid];
            out[b * (1 + D) + 1 + tid] = a;
        }
        return;
    }

    // ======================= gather path =======================
    __shared__ float urel_s[64];
    __shared__ float Wm[256], bbias[16];
    __shared__ float tmp1s[4][8][17];
    __shared__ float ev1s[4][8][17];
    __shared__ float out1s[4][8][17];
    __shared__ float ev0s[4][16];
    __shared__ float p0s[4][8];
    __shared__ float t0s[4][17];
    __shared__ float tfs[4][17];
    __shared__ int   headflag;

    int gb  = blockIdx.x - NDIFF;
    int bsl = tid >> 5, n = (tid >> 2) & 7, q = tid & 3;
    int bs  = gb * 4 + bsl;
    int bq  = bs >> 6;                 // same batch for all 4 bs in block

    Wm[tid]       = __ldg(agg_W + tid);
    Wm[tid + 128] = __ldg(agg_W + tid + 128);
    if (tid < 16) bbias[tid] = __ldg(agg_b + tid);

    // per-block urel table: urel[r] = mean_d usr[u[bq]][d]*rel[r][d]
    if (tid < 64) {
        const float4* uu = (const float4*)usr_emb + (size_t)__ldg(u + bq) * 4;
        const float4* rv = (const float4*)rel_emb + tid * 4;
        float4 a0 = __ldg(uu), a1 = __ldg(uu + 1), a2 = __ldg(uu + 2), a3 = __ldg(uu + 3);
        float4 c0 = __ldg(rv), c1 = __ldg(rv + 1), c2 = __ldg(rv + 2), c3 = __ldg(rv + 3);
        float sd = a0.x*c0.x + a0.y*c0.y + a0.z*c0.z + a0.w*c0.w
                 + a1.x*c1.x + a1.y*c1.y + a1.z*c1.z + a1.w*c1.w
                 + a2.x*c2.x + a2.y*c2.y + a2.z*c2.z + a2.w*c2.w
                 + a3.x*c3.x + a3.y*c3.y + a3.z*c3.z + a3.w*c3.w;
        urel_s[tid] = sd * (1.0f / 16.0f);
    }

    // -------- index chain (per warp = one bs) --------
    const float4* E = (const float4*)ent_emb;
    int e0 = __ldg(click_seq + bs);
    int e1 = __ldg(adj_ent + (size_t)e0 * KNB + n);
    int r0 = __ldg(adj_rel + (size_t)e0 * KNB + n);
    int2 e2p = __ldg((const int2*)(adj_ent + (size_t)e1 * KNB) + q);
    int2 r1p = __ldg((const int2*)(adj_rel + (size_t)e1 * KNB) + q);

    float4 e1v = __ldg(E + (size_t)e1 * 4 + q);
    if (n == 0) {
        float4 vv = __ldg(E + (size_t)e0 * 4 + q);
        ev0s[bsl][q*4+0] = vv.x; ev0s[bsl][q*4+1] = vv.y;
        ev0s[bsl][q*4+2] = vv.z; ev0s[bsl][q*4+3] = vv.w;
    }

    __syncthreads();   // urel_s ready

    // -------- p1 softmax (no max-sub: |score| << 1) --------
    float ew0 = __expf(urel_s[r1p.x]);
    float ew1 = __expf(urel_s[r1p.y]);
    float sum = ew0 + ew1;
    sum += __shfl_xor_sync(0xffffffffu, sum, 1);
    sum += __shfl_xor_sync(0xffffffffu, sum, 2);
    float inv = __fdividef(1.f, sum);
    float w0 = ew0 * inv, w1 = ew1 * inv;

    // distribute all 8 (e2, w) across the 4-lane group
    int lb = (tid & 31) & ~3;
    int eA0 = __shfl_sync(0xffffffffu, e2p.x, lb+0), eB0 = __shfl_sync(0xffffffffu, e2p.y, lb+0);
    int eA1 = __shfl_sync(0xffffffffu, e2p.x, lb+1), eB1 = __shfl_sync(0xffffffffu, e2p.y, lb+1);
    int eA2 = __shfl_sync(0xffffffffu, e2p.x, lb+2), eB2 = __shfl_sync(0xffffffffu, e2p.y, lb+2);
    int eA3 = __shfl_sync(0xffffffffu, e2p.x, lb+3), eB3 = __shfl_sync(0xffffffffu, e2p.y, lb+3);
    float wA0 = __shfl_sync(0xffffffffu, w0, lb+0), wB0 = __shfl_sync(0xffffffffu, w1, lb+0);
    float wA1 = __shfl_sync(0xffffffffu, w0, lb+1), wB1 = __shfl_sync(0xffffffffu, w1, lb+1);
    float wA2 = __shfl_sync(0xffffffffu, w0, lb+2), wB2 = __shfl_sync(0xffffffffu, w1, lb+2);
    float wA3 = __shfl_sync(0xffffffffu, w0, lb+3), wB3 = __shfl_sync(0xffffffffu, w1, lb+3);

    // -------- the hot random gather: 8 independent float4 loads --------
    float4 v0 = __ldg(E + (size_t)eA0 * 4 + q);
    float4 v1 = __ldg(E + (size_t)eB0 * 4 + q);
    float4 v2 = __ldg(E + (size_t)eA1 * 4 + q);
    float4 v3 = __ldg(E + (size_t)eB1 * 4 + q);
    float4 v4 = __ldg(E + (size_t)eA2 * 4 + q);
    float4 v5 = __ldg(E + (size_t)eB2 * 4 + q);
    float4 v6 = __ldg(E + (size_t)eA3 * 4 + q);
    float4 v7 = __ldg(E + (size_t)eB3 * 4 + q);

    float4 acc;
    acc.x = wA0*v0.x + wB0*v1.x + wA1*v2.x + wB1*v3.x
          + wA2*v4.x + wB2*v5.x + wA3*v6.x + wB3*v7.x;
    acc.y = wA0*v0.y + wB0*v1.y + wA1*v2.y + wB1*v3.y
          + wA2*v4.y + wB2*v5.y + wA3*v6.y + wB3*v7.y;
    acc.z = wA0*v0.z + wB0*v1.z + wA1*v2.z + wB1*v3.z
          + wA2*v4.z + wB2*v5.z + wA3*v6.z + wB3*v7.z;
    acc.w = wA0*v0.w + wB0*v1.w + wA1*v2.w + wB1*v3.w
          + wA2*v4.w + wB2*v5.w + wA3*v6.w + wB3*v7.w;

    int qq = q * 4;
    tmp1s[bsl][n][qq+0] = e1v.x + acc.x;
    tmp1s[bsl][n][qq+1] = e1v.y + acc.y;
    tmp1s[bsl][n][qq+2] = e1v.z + acc.z;
    tmp1s[bsl][n][qq+3] = e1v.w + acc.w;
    ev1s[bsl][n][qq+0] = e1v.x;
    ev1s[bsl][n][qq+1] = e1v.y;
    ev1s[bsl][n][qq+2] = e1v.z;
    ev1s[bsl][n][qq+3] = e1v.w;

    // -------- p0 softmax (over n within warp; q-redundant; no max-sub) -----
    {
        float e = __expf(urel_s[r0]);
        float su = e;
        su += __shfl_xor_sync(0xffffffffu, su, 4);
        su += __shfl_xor_sync(0xffffffffu, su, 8);
        su += __shfl_xor_sync(0xffffffffu, su, 16);
        if (q == 0) p0s[bsl][n] = __fdividef(e, su);
    }
    __syncthreads();

    // -------- hop1 linear + sigmoid (4 outputs/thread); t0 partial --------
#pragma unroll
    for (int j = 0; j < 4; j++) {
        int o = tid + 128 * j;
        int bl = o >> 7, n2 = (o >> 4) & 7, dp = o & 15;
        float a = bbias[dp];
#pragma unroll
        for (int d = 0; d < 16; d++)
            a = fmaf(tmp1s[bl][n2][d], Wm[d * 16 + dp], a);
        out1s[bl][n2][dp] = fsigmoid(a);
    }
    if (tid < 64) {
        int bl = tid >> 4, d = tid & 15;
        float t0 = ev0s[bl][d];
#pragma unroll
        for (int k = 0; k < 8; k++)
            t0 = fmaf(p0s[bl][k], ev1s[bl][k][d], t0);
        t0s[bl][d] = t0;
    }
    __syncthreads();

    if (tid < 64) {
        int bl = tid >> 4, d = tid & 15;
        float a = bbias[d];
#pragma unroll
        for (int d2 = 0; d2 < 16; d2++)
            a = fmaf(t0s[bl][d2], Wm[d2 * 16 + d], a);
        float o0 = fsigmoid(a);
        float tf = o0;
#pragma unroll
        for (int k = 0; k < 8; k++)
            tf = fmaf(p0s[bl][k], out1s[bl][k][d], tf);
        tfs[bl][d] = tf;
    }
    __syncthreads();

    if (tid < 64) {
        int bl = tid >> 4, d = tid & 15;
        float a = bbias[d];
#pragma unroll
        for (int d2 = 0; d2 < 16; d2++)
            a = fmaf(tfs[bl][d2], Wm[d2 * 16 + d], a);
        g_item[(size_t)(gb * 4 + bl) * 16 + d] = fmaxf(tanhf(a), 0.f);
    }

    // -------- last-block-per-batch fusion head (mod-16 counter) --------
    __threadfence();          // each thread releases its own g_item writes
    __syncthreads();          // order all fences before the atomic
    if (tid == 0) {
        unsigned int old = atomicAdd(&g_cnt[bq], 1u);
        headflag = ((old & 15u) == 15u);
    }
    __syncthreads();
    if (!headflag) return;

    __shared__ float ps[8][16], pm[8][16], fus[32], hh[64];
    {
        int d = tid & 15, sc = tid >> 4;
        float s = 0.f, mmx = -1e30f;
#pragma unroll
        for (int j = 0; j < 8; j++) {
            float vv = __ldcg(g_item + ((size_t)bq * S + sc * 8 + j) * D + d);
            s += vv;
            mmx = fmaxf(mmx, vv);
        }
        ps[sc][d] = s;
        pm[sc][d] = mmx;
    }
    __syncthreads();
    if (tid < 16) {
        float s = 0.f, mmx = -1e30f;
#pragma unroll
        for (int c = 0; c < 8; c++) { s += ps[c][tid]; mmx = fmaxf(mmx, pm[c][tid]); }
        fus[tid]      = fmaxf(s, 0.f);
        fus[16 + tid] = fmaxf(mmx, 0.f);
    }
    __syncthreads();
    if (tid < 64) {
        float a = __ldg(fc1_b + tid);
#pragma unroll
        for (int i = 0; i < 32; i++)
            a = fmaf(fus[i], __ldg(fc1_W + i * 64 + tid), a);
        hh[tid] = fmaxf(a, 0.f);
    }
    __syncthreads();
    if (tid < 16) {
        float a = __ldg(fc2_b + tid);
#pragma unroll
        for (int i = 0; i < 64; i++)
            a = fmaf(hh[i], __ldg(fc2_W + i * D + tid), a);
        float f = fmaxf(a, 0.f);
        float p = f * __ldg(ent_emb + (size_t)__ldg(v + bq) * D + tid);
        p += __shfl_xor_sync(0xffffu, p, 8);
        p += __shfl_xor_sync(0xffffu, p, 4);
        p += __shfl_xor_sync(0xffffu, p, 2);
        p += __shfl_xor_sync(0xffffu, p, 1);
        if (tid == 0)
            out[bq * (1 + D)] = fsigmoid(p);
    }
}

// ---------------------------------------------------------------------------
extern "C" void kernel_launch(void* const* d_in, const int* in_sizes, int n_in,
                              void* d_out, int out_size)
{
    const float* usr_emb  = (const float*)d_in[0];
    const float* ent_emb  = (const float*)d_in[1];
    const float* rel_emb  = (const float*)d_in[2];
    const float* agg_W    = (const float*)d_in[3];
    const float* agg_b    = (const float*)d_in[4];
    const float* fc1_W    = (const float*)d_in[5];
    const float* fc1_b    = (const float*)d_in[6];
    const float* fc2_W    = (const float*)d_in[7];
    const float* fc2_b    = (const float*)d_in[8];
    const float* mlp_W1   = (const float*)d_in[9];
    const float* mlp_b1   = (const float*)d_in[10];
    const float* mlp_W2   = (const float*)d_in[11];
    const float* mlp_b2   = (const float*)d_in[12];
    const float* mlp_W3   = (const float*)d_in[13];
    const float* mlp_b3   = (const float*)d_in[14];
    const float* mlp_W4   = (const float*)d_in[15];
    const float* mlp_b4   = (const float*)d_in[16];
    const float* se1      = (const float*)d_in[17];
    const float* se2      = (const float*)d_in[18];
    const float* se3      = (const float*)d_in[19];
    const float* noise_e  = (const float*)d_in[20];
    const int*   u        = (const int*)d_in[21];
    const int*   v        = (const int*)d_in[22];
    const int*   click    = (const int*)d_in[23];
    const int*   adj_ent  = (const int*)d_in[24];
    const int*   adj_rel  = (const int*)d_in[25];
    const int*   t        = (const int*)d_in[26];
    float* out = (float*)d_out;

    fused_kernel<<<NDIFF + NGATH, 128>>>(ent_emb, rel_emb, agg_W, agg_b, usr_emb,
                                         mlp_W1, mlp_b1, mlp_W2, mlp_b2,
                                         mlp_W3, mlp_b3, mlp_W4, mlp_b4,
                                         se1, se2, se3, noise_e,
                                         fc1_W, fc1_b, fc2_W, fc2_b,
                                         u, v, t, click, adj_ent, adj_rel, out);
}

// round 11
// speedup vs baseline: 1.5061x; 1.0005x over previous
#include <cuda_runtime.h>
#include <cuda_bf16.h>
#include <math.h>

#define B 512
#define S 64
#define KNB 8
#define D 16
#define NSTEPS 100
#define NUNITS 128

#define BS    (B*S)       // 32768
#define NDIFF (B)         // 512 diffusion blocks (1 batch each)
#define NGATH (BS/4)      // 8192 gather blocks (4 (b,s) each)

// ---- device scratch (static, allocation-free) ----
__device__ float g_item[BS * D];
__device__ unsigned int g_cnt[B];   // monotonic; head = (old & 15) == 15

__device__ __forceinline__ float fsigmoid(float a) {
    return __fdividef(1.f, 1.f + __expf(-a));
}

// ---------------------------------------------------------------------------
// Single fused kernel, 128-thread blocks.
//   blocks [0, NDIFF)            : diffusion MLP, 1 batch each
//   blocks [NDIFF, NDIFF+NGATH)  : full KGCN chain for 4 (b,s); 16th-arriving
//                                  block per batch runs the fusion head.
// ---------------------------------------------------------------------------
__global__ __launch_bounds__(128) void fused_kernel(
    const float* __restrict__ ent_emb,
    const float* __restrict__ rel_emb,
    const float* __restrict__ agg_W, const float* __restrict__ agg_b,
    const float* __restrict__ usr_emb,
    const float* __restrict__ W1, const float* __restrict__ b1,
    const float* __restrict__ W2, const float* __restrict__ b2,
    const float* __restrict__ W3, const float* __restrict__ b3,
    const float* __restrict__ W4, const float* __restrict__ b4,
    const float* __restrict__ se1, const float* __restrict__ se2,
    const float* __restrict__ se3,
    const float* __restrict__ noise_e,
    const float* __restrict__ fc1_W, const float* __restrict__ fc1_b,
    const float* __restrict__ fc2_W, const float* __restrict__ fc2_b,
    const int* __restrict__ u, const int* __restrict__ v,
    const int* __restrict__ t,
    const int* __restrict__ click_seq,
    const int* __restrict__ adj_ent, const int* __restrict__ adj_rel,
    float* __restrict__ out)
{
    int tid = threadIdx.x;

    // ======================= diffusion path =======================
    if (blockIdx.x < NDIFF) {
        __shared__ float red[128];
        __shared__ float xs[16], ha[128], hb[128], p4[8][16];
        int b = blockIdx.x;
        int tb = __ldg(t + b);

        // alpha-bar via parallel log1p sum
        float lg = 0.f;
        if (tid < NSTEPS && tid <= tb) {
            float z = -6.f + 12.f * (float)tid / 99.f;
            float beta = fsigmoid(z) * (0.005f - 1e-5f) + 1e-5f;
            lg = log1pf(-beta);
        }
        red[tid] = lg;
        __syncthreads();
#pragma unroll
        for (int st = 64; st > 0; st >>= 1) {
            if (tid < st) red[tid] += red[tid + st];
            __syncthreads();
        }
        float ap  = __expf(red[0]);
        float ab  = sqrtf(ap);
        float omb = sqrtf(1.f - ap);

        if (tid < 16)
            xs[tid] = __ldg(usr_emb + (size_t)__ldg(u + b) * D + tid) * ab
                    + __ldg(noise_e + b * D + tid) * omb;
        __syncthreads();
        {
            float a = __ldg(b1 + tid) + __ldg(se1 + tb * NUNITS + tid);
#pragma unroll
            for (int d = 0; d < 16; d++)
                a = fmaf(xs[d], __ldg(W1 + d * NUNITS + tid), a);
            ha[tid] = fmaxf(a, 0.f);
        }
        __syncthreads();
        {
            float a0 = 0.f, a1 = 0.f, a2 = 0.f, a3 = 0.f;
#pragma unroll
            for (int i = 0; i < 128; i += 4) {
                a0 = fmaf(ha[i+0], __ldg(W2 + (i+0) * NUNITS + tid), a0);
                a1 = fmaf(ha[i+1], __ldg(W2 + (i+1) * NUNITS + tid), a1);
                a2 = fmaf(ha[i+2], __ldg(W2 + (i+2) * NUNITS + tid), a2);
                a3 = fmaf(ha[i+3], __ldg(W2 + (i+3) * NUNITS + tid), a3);
            }
            float a = __ldg(b2 + tid) + __ldg(se2 + tb * NUNITS + tid)
                    + ((a0 + a1) + (a2 + a3));
            hb[tid] = fmaxf(a, 0.f);
        }
        __syncthreads();
        {
            float a0 = 0.f, a1 = 0.f, a2 = 0.f, a3 = 0.f;
#pragma unroll
            for (int i = 0; i < 128; i += 4) {
                a0 = fmaf(hb[i+0], __ldg(W3 + (i+0) * NUNITS + tid), a0);
                a1 = fmaf(hb[i+1], __ldg(W3 + (i+1) * NUNITS + tid), a1);
                a2 = fmaf(hb[i+2], __ldg(W3 + (i+2) * NUNITS + tid), a2);
                a3 = fmaf(hb[i+3], __ldg(W3 + (i+3) * NUNITS + tid), a3);
            }
            float a = __ldg(b3 + tid) + __ldg(se3 + tb * NUNITS + tid)
                    + ((a0 + a1) + (a2 + a3));
            ha[tid] = fmaxf(a, 0.f);
        }
        __syncthreads();
        {
            int g = tid >> 4, d = tid & 15;
            float a = 0.f;
#pragma unroll
            for (int i = 0; i < 16; i++)
                a = fmaf(ha[g * 16 + i], __ldg(W4 + (g * 16 + i) * D + d), a);
            p4[g][d] = a;
        }
        __syncthreads();
        if (tid < 16) {
            float a = __ldg(b4 + tid);
#pragma unroll
            for (int g = 0; g < 8; g++) a += p4[g][tid];
            out[b * (1 + D) + 1 + tid] = a;
        }
        return;
    }

    // ======================= gather path =======================
    __shared__ float urel_s[64];
    __shared__ float Wm[256], bbias[16];
    __shared__ float tmp1s[4][8][17];
    __shared__ float ev1s[4][8][17];
    __shared__ float out1s[4][8][17];
    __shared__ float ev0s[4][16];
    __shared__ float p0s[4][8];
    __shared__ float t0s[4][17];
    __shared__ float tfs[4][17];
    __shared__ int   headflag;

    int gb  = blockIdx.x - NDIFF;
    int bsl = tid >> 5, n = (tid >> 2) & 7, q = tid & 3;
    int bs  = gb * 4 + bsl;
    int bq  = bs >> 6;                 // same batch for all 4 bs in block

    Wm[tid]       = __ldg(agg_W + tid);
    Wm[tid + 128] = __ldg(agg_W + tid + 128);
    if (tid < 16) bbias[tid] = __ldg(agg_b + tid);

    // per-block urel table: urel[r] = mean_d usr[u[bq]][d]*rel[r][d]
    if (tid < 64) {
        const float4* uu = (const float4*)usr_emb + (size_t)__ldg(u + bq) * 4;
        const float4* rv = (const float4*)rel_emb + tid * 4;
        float4 a0 = __ldg(uu), a1 = __ldg(uu + 1), a2 = __ldg(uu + 2), a3 = __ldg(uu + 3);
        float4 c0 = __ldg(rv), c1 = __ldg(rv + 1), c2 = __ldg(rv + 2), c3 = __ldg(rv + 3);
        float sd = a0.x*c0.x + a0.y*c0.y + a0.z*c0.z + a0.w*c0.w
                 + a1.x*c1.x + a1.y*c1.y + a1.z*c1.z + a1.w*c1.w
                 + a2.x*c2.x + a2.y*c2.y + a2.z*c2.z + a2.w*c2.w
                 + a3.x*c3.x + a3.y*c3.y + a3.z*c3.z + a3.w*c3.w;
        urel_s[tid] = sd * (1.0f / 16.0f);
    }

    // -------- index chain (per warp = one bs) --------
    const float4* E = (const float4*)ent_emb;
    int e0 = __ldg(click_seq + bs);
    int e1 = __ldg(adj_ent + (size_t)e0 * KNB + n);
    int r0 = __ldg(adj_rel + (size_t)e0 * KNB + n);
    int2 e2p = __ldg((const int2*)(adj_ent + (size_t)e1 * KNB) + q);
    int2 r1p = __ldg((const int2*)(adj_rel + (size_t)e1 * KNB) + q);

    float4 e1v = __ldg(E + (size_t)e1 * 4 + q);
    if (n == 0) {
        float4 vv = __ldg(E + (size_t)e0 * 4 + q);
        ev0s[bsl][q*4+0] = vv.x; ev0s[bsl][q*4+1] = vv.y;
        ev0s[bsl][q*4+2] = vv.z; ev0s[bsl][q*4+3] = vv.w;
    }

    __syncthreads();   // urel_s ready

    // -------- p1 softmax (no max-sub: |score| << 1) --------
    float ew0 = __expf(urel_s[r1p.x]);
    float ew1 = __expf(urel_s[r1p.y]);
    float sum = ew0 + ew1;
    sum += __shfl_xor_sync(0xffffffffu, sum, 1);
    sum += __shfl_xor_sync(0xffffffffu, sum, 2);
    float inv = __fdividef(1.f, sum);
    float w0 = ew0 * inv, w1 = ew1 * inv;

    // distribute all 8 (e2, w) across the 4-lane group
    int lb = (tid & 31) & ~3;
    int eA0 = __shfl_sync(0xffffffffu, e2p.x, lb+0), eB0 = __shfl_sync(0xffffffffu, e2p.y, lb+0);
    int eA1 = __shfl_sync(0xffffffffu, e2p.x, lb+1), eB1 = __shfl_sync(0xffffffffu, e2p.y, lb+1);
    int eA2 = __shfl_sync(0xffffffffu, e2p.x, lb+2), eB2 = __shfl_sync(0xffffffffu, e2p.y, lb+2);
    int eA3 = __shfl_sync(0xffffffffu, e2p.x, lb+3), eB3 = __shfl_sync(0xffffffffu, e2p.y, lb+3);
    float wA0 = __shfl_sync(0xffffffffu, w0, lb+0), wB0 = __shfl_sync(0xffffffffu, w1, lb+0);
    float wA1 = __shfl_sync(0xffffffffu, w0, lb+1), wB1 = __shfl_sync(0xffffffffu, w1, lb+1);
    float wA2 = __shfl_sync(0xffffffffu, w0, lb+2), wB2 = __shfl_sync(0xffffffffu, w1, lb+2);
    float wA3 = __shfl_sync(0xffffffffu, w0, lb+3), wB3 = __shfl_sync(0xffffffffu, w1, lb+3);

    // -------- the hot random gather: 8 independent float4 loads --------
    float4 v0 = __ldg(E + (size_t)eA0 * 4 + q);
    float4 v1 = __ldg(E + (size_t)eB0 * 4 + q);
    float4 v2 = __ldg(E + (size_t)eA1 * 4 + q);
    float4 v3 = __ldg(E + (size_t)eB1 * 4 + q);
    float4 v4 = __ldg(E + (size_t)eA2 * 4 + q);
    float4 v5 = __ldg(E + (size_t)eB2 * 4 + q);
    float4 v6 = __ldg(E + (size_t)eA3 * 4 + q);
    float4 v7 = __ldg(E + (size_t)eB3 * 4 + q);

    float4 acc;
    acc.x = wA0*v0.x + wB0*v1.x + wA1*v2.x + wB1*v3.x
          + wA2*v4.x + wB2*v5.x + wA3*v6.x + wB3*v7.x;
    acc.y = wA0*v0.y + wB0*v1.y + wA1*v2.y + wB1*v3.y
          + wA2*v4.y + wB2*v5.y + wA3*v6.y + wB3*v7.y;
    acc.z = wA0*v0.z + wB0*v1.z + wA1*v2.z + wB1*v3.z
          + wA2*v4.z + wB2*v5.z + wA3*v6.z + wB3*v7.z;
    acc.w = wA0*v0.w + wB0*v1.w + wA1*v2.w + wB1*v3.w
          + wA2*v4.w + wB2*v5.w + wA3*v6.w + wB3*v7.w;

    int qq = q * 4;
    tmp1s[bsl][n][qq+0] = e1v.x + acc.x;
    tmp1s[bsl][n][qq+1] = e1v.y + acc.y;
    tmp1s[bsl][n][qq+2] = e1v.z + acc.z;
    tmp1s[bsl][n][qq+3] = e1v.w + acc.w;
    ev1s[bsl][n][qq+0] = e1v.x;
    ev1s[bsl][n][qq+1] = e1v.y;
    ev1s[bsl][n][qq+2] = e1v.z;
    ev1s[bsl][n][qq+3] = e1v.w;

    // -------- p0 softmax (over n within warp; q-redundant; no max-sub) -----
    {
        float e = __expf(urel_s[r0]);
        float su = e;
        su += __shfl_xor_sync(0xffffffffu, su, 4);
        su += __shfl_xor_sync(0xffffffffu, su, 8);
        su += __shfl_xor_sync(0xffffffffu, su, 16);
        if (q == 0) p0s[bsl][n] = __fdividef(e, su);
    }
    __syncthreads();

    // -------- hop1 linear + sigmoid (4 outputs/thread); t0 partial --------
#pragma unroll
    for (int j = 0; j < 4; j++) {
        int o = tid + 128 * j;
        int bl = o >> 7, n2 = (o >> 4) & 7, dp = o & 15;
        float a = bbias[dp];
#pragma unroll
        for (int d = 0; d < 16; d++)
            a = fmaf(tmp1s[bl][n2][d], Wm[d * 16 + dp], a);
        out1s[bl][n2][dp] = fsigmoid(a);
    }
    if (tid < 64) {
        int bl = tid >> 4, d = tid & 15;
        float t0 = ev0s[bl][d];
#pragma unroll
        for (int k = 0; k < 8; k++)
            t0 = fmaf(p0s[bl][k], ev1s[bl][k][d], t0);
        t0s[bl][d] = t0;
    }
    __syncthreads();

    if (tid < 64) {
        int bl = tid >> 4, d = tid & 15;
        float a = bbias[d];
#pragma unroll
        for (int d2 = 0; d2 < 16; d2++)
            a = fmaf(t0s[bl][d2], Wm[d2 * 16 + d], a);
        float o0 = fsigmoid(a);
        float tf = o0;
#pragma unroll
        for (int k = 0; k < 8; k++)
            tf = fmaf(p0s[bl][k], out1s[bl][k][d], tf);
        tfs[bl][d] = tf;
    }
    __syncthreads();

    if (tid < 64) {
        int bl = tid >> 4, d = tid & 15;
        float a = bbias[d];
#pragma unroll
        for (int d2 = 0; d2 < 16; d2++)
            a = fmaf(tfs[bl][d2], Wm[d2 * 16 + d], a);
        g_item[(size_t)(gb * 4 + bl) * 16 + d] = fmaxf(tanhf(a), 0.f);
    }

    // -------- last-block-per-batch fusion head (mod-16 counter) --------
    __threadfence();          // each thread releases its own g_item writes
    __syncthreads();          // order all fences before the atomic
    if (tid == 0) {
        unsigned int old = atomicAdd(&g_cnt[bq], 1u);
        headflag = ((old & 15u) == 15u);
    }
    __syncthreads();
    if (!headflag) return;

    __shared__ float ps[8][16], pm[8][16], fus[32], hh[64];
    {
        int d = tid & 15, sc = tid >> 4;
        float s = 0.f, mmx = -1e30f;
#pragma unroll
        for (int j = 0; j < 8; j++) {
            float vv = __ldcg(g_item + ((size_t)bq * S + sc * 8 + j) * D + d);
            s += vv;
            mmx = fmaxf(mmx, vv);
        }
        ps[sc][d] = s;
        pm[sc][d] = mmx;
    }
    __syncthreads();
    if (tid < 16) {
        float s = 0.f, mmx = -1e30f;
#pragma unroll
        for (int c = 0; c < 8; c++) { s += ps[c][tid]; mmx = fmaxf(mmx, pm[c][tid]); }
        fus[tid]      = fmaxf(s, 0.f);
        fus[16 + tid] = fmaxf(mmx, 0.f);
    }
    __syncthreads();
    if (tid < 64) {
        float a = __ldg(fc1_b + tid);
#pragma unroll
        for (int i = 0; i < 32; i++)
            a = fmaf(fus[i], __ldg(fc1_W + i * 64 + tid), a);
        hh[tid] = fmaxf(a, 0.f);
    }
    __syncthreads();
    if (tid < 16) {
        float a = __ldg(fc2_b + tid);
#pragma unroll
        for (int i = 0; i < 64; i++)
            a = fmaf(hh[i], __ldg(fc2_W + i * D + tid), a);
        float f = fmaxf(a, 0.f);
        float p = f * __ldg(ent_emb + (size_t)__ldg(v + bq) * D + tid);
        p += __shfl_xor_sync(0xffffu, p, 8);
        p += __shfl_xor_sync(0xffffu, p, 4);
        p += __shfl_xor_sync(0xffffu, p, 2);
        p += __shfl_xor_sync(0xffffu, p, 1);
        if (tid == 0)
            out[bq * (1 + D)] = fsigmoid(p);
    }
}

// ---------------------------------------------------------------------------
extern "C" void kernel_launch(void* const* d_in, const int* in_sizes, int n_in,
                              void* d_out, int out_size)
{
    const float* usr_emb  = (const float*)d_in[0];
    const float* ent_emb  = (const float*)d_in[1];
    const float* rel_emb  = (const float*)d_in[2];
    const float* agg_W    = (const float*)d_in[3];
    const float* agg_b    = (const float*)d_in[4];
    const float* fc1_W    = (const float*)d_in[5];
    const float* fc1_b    = (const float*)d_in[6];
    const float* fc2_W    = (const float*)d_in[7];
    const float* fc2_b    = (const float*)d_in[8];
    const float* mlp_W1   = (const float*)d_in[9];
    const float* mlp_b1   = (const float*)d_in[10];
    const float* mlp_W2   = (const float*)d_in[11];
    const float* mlp_b2   = (const float*)d_in[12];
    const float* mlp_W3   = (const float*)d_in[13];
    const float* mlp_b3   = (const float*)d_in[14];
    const float* mlp_W4   = (const float*)d_in[15];
    const float* mlp_b4   = (const float*)d_in[16];
    const float* se1      = (const float*)d_in[17];
    const float* se2      = (const float*)d_in[18];
    const float* se3      = (const float*)d_in[19];
    const float* noise_e  = (const float*)d_in[20];
    const int*   u        = (const int*)d_in[21];
    const int*   v        = (const int*)d_in[22];
    const int*   click    = (const int*)d_in[23];
    const int*   adj_ent  = (const int*)d_in[24];
    const int*   adj_rel  = (const int*)d_in[25];
    const int*   t        = (const int*)d_in[26];
    float* out = (float*)d_out;

    fused_kernel<<<NDIFF + NGATH, 128>>>(ent_emb, rel_emb, agg_W, agg_b, usr_emb,
                                         mlp_W1, mlp_b1, mlp_W2, mlp_b2,
                                         mlp_W3, mlp_b3, mlp_W4, mlp_b4,
                                         se1, se2, se3, noise_e,
                                         fc1_W, fc1_b, fc2_W, fc2_b,
                                         u, v, t, click, adj_ent, adj_rel, out);
}

// round 12
// speedup vs baseline: 1.5175x; 1.0075x over previous
#include <cuda_runtime.h>
#include <cuda_bf16.h>
#include <math.h>

#define B 512
#define S 64
#define KNB 8
#define D 16
#define NSTEPS 100
#define NUNITS 128

#define BS    (B*S)       // 32768
#define NDIFF (B)         // 512 diffusion blocks (1 batch each)
#define NGATH (BS/4)      // 8192 gather blocks (4 (b,s) each)

// ---- device scratch (static, allocation-free) ----
__device__ float g_item[BS * D];
__device__ unsigned int g_cnt[B];   // monotonic; head = (old & 15) == 15

__device__ __forceinline__ float fsigmoid(float a) {
    return __fdividef(1.f, 1.f + __expf(-a));
}

// ---------------------------------------------------------------------------
// Single fused kernel, 128-thread blocks.
//   blocks [0, NDIFF)            : diffusion MLP, 1 batch each
//   blocks [NDIFF, NDIFF+NGATH)  : full KGCN chain for 4 (b,s); 16th-arriving
//                                  block per batch runs the fusion head.
// ---------------------------------------------------------------------------
__global__ __launch_bounds__(128) void fused_kernel(
    const float* __restrict__ ent_emb,
    const float* __restrict__ rel_emb,
    const float* __restrict__ agg_W, const float* __restrict__ agg_b,
    const float* __restrict__ usr_emb,
    const float* __restrict__ W1, const float* __restrict__ b1,
    const float* __restrict__ W2, const float* __restrict__ b2,
    const float* __restrict__ W3, const float* __restrict__ b3,
    const float* __restrict__ W4, const float* __restrict__ b4,
    const float* __restrict__ se1, const float* __restrict__ se2,
    const float* __restrict__ se3,
    const float* __restrict__ noise_e,
    const float* __restrict__ fc1_W, const float* __restrict__ fc1_b,
    const float* __restrict__ fc2_W, const float* __restrict__ fc2_b,
    const int* __restrict__ u, const int* __restrict__ v,
    const int* __restrict__ t,
    const int* __restrict__ click_seq,
    const int* __restrict__ adj_ent, const int* __restrict__ adj_rel,
    float* __restrict__ out)
{
    int tid = threadIdx.x;

    // ======================= diffusion path =======================
    if (blockIdx.x < NDIFF) {
        __shared__ float red[128];
        __shared__ float xs[16], ha[128], hb[128], p4[8][16];
        int b = blockIdx.x;
        int tb = __ldg(t + b);

        float lg = 0.f;
        if (tid < NSTEPS && tid <= tb) {
            float z = -6.f + 12.f * (float)tid / 99.f;
            float beta = fsigmoid(z) * (0.005f - 1e-5f) + 1e-5f;
            lg = log1pf(-beta);
        }
        red[tid] = lg;
        __syncthreads();
#pragma unroll
        for (int st = 64; st > 0; st >>= 1) {
            if (tid < st) red[tid] += red[tid + st];
            __syncthreads();
        }
        float ap  = __expf(red[0]);
        float ab  = sqrtf(ap);
        float omb = sqrtf(1.f - ap);

        if (tid < 16)
            xs[tid] = __ldg(usr_emb + (size_t)__ldg(u + b) * D + tid) * ab
                    + __ldg(noise_e + b * D + tid) * omb;
        __syncthreads();
        {
            float a = __ldg(b1 + tid) + __ldg(se1 + tb * NUNITS + tid);
#pragma unroll
            for (int d = 0; d < 16; d++)
                a = fmaf(xs[d], __ldg(W1 + d * NUNITS + tid), a);
            ha[tid] = fmaxf(a, 0.f);
        }
        __syncthreads();
        {
            float a0 = 0.f, a1 = 0.f, a2 = 0.f, a3 = 0.f;
#pragma unroll
            for (int i = 0; i < 128; i += 4) {
                a0 = fmaf(ha[i+0], __ldg(W2 + (i+0) * NUNITS + tid), a0);
                a1 = fmaf(ha[i+1], __ldg(W2 + (i+1) * NUNITS + tid), a1);
                a2 = fmaf(ha[i+2], __ldg(W2 + (i+2) * NUNITS + tid), a2);
                a3 = fmaf(ha[i+3], __ldg(W2 + (i+3) * NUNITS + tid), a3);
            }
            float a = __ldg(b2 + tid) + __ldg(se2 + tb * NUNITS + tid)
                    + ((a0 + a1) + (a2 + a3));
            hb[tid] = fmaxf(a, 0.f);
        }
        __syncthreads();
        {
            float a0 = 0.f, a1 = 0.f, a2 = 0.f, a3 = 0.f;
#pragma unroll
            for (int i = 0; i < 128; i += 4) {
                a0 = fmaf(hb[i+0], __ldg(W3 + (i+0) * NUNITS + tid), a0);
                a1 = fmaf(hb[i+1], __ldg(W3 + (i+1) * NUNITS + tid), a1);
                a2 = fmaf(hb[i+2], __ldg(W3 + (i+2) * NUNITS + tid), a2);
                a3 = fmaf(hb[i+3], __ldg(W3 + (i+3) * NUNITS + tid), a3);
            }
            float a = __ldg(b3 + tid) + __ldg(se3 + tb * NUNITS + tid)
                    + ((a0 + a1) + (a2 + a3));
            ha[tid] = fmaxf(a, 0.f);
        }
        __syncthreads();
        {
            int g = tid >> 4, d = tid & 15;
            float a = 0.f;
#pragma unroll
            for (int i = 0; i < 16; i++)
                a = fmaf(ha[g * 16 + i], __ldg(W4 + (g * 16 + i) * D + d), a);
            p4[g][d] = a;
        }
        __syncthreads();
        if (tid < 16) {
            float a = __ldg(b4 + tid);
#pragma unroll
            for (int g = 0; g < 8; g++) a += p4[g][tid];
            out[b * (1 + D) + 1 + tid] = a;
        }
        return;
    }

    // ======================= gather path =======================
    __shared__ float urel_s[64];
    __shared__ float Wm[256], bbias[16];
    __shared__ float tmp1s[4][8][20];   // float4-aligned rows (80B)
    __shared__ float out1s[4][8][18];   // conflict-tuned
    __shared__ float p0s[4][8];
    __shared__ float t0s[4][20];
    __shared__ float tfs[4][17];
    __shared__ int   headflag;

    int gb  = blockIdx.x - NDIFF;
    int bsl = tid >> 5, n = (tid >> 2) & 7, q = tid & 3;
    int bs  = gb * 4 + bsl;
    int bq  = bs >> 6;                 // same batch for all 4 bs in block

    Wm[tid]       = __ldg(agg_W + tid);
    Wm[tid + 128] = __ldg(agg_W + tid + 128);
    if (tid < 16) bbias[tid] = __ldg(agg_b + tid);

    // per-block urel table
    if (tid < 64) {
        const float4* uu = (const float4*)usr_emb + (size_t)__ldg(u + bq) * 4;
        const float4* rv = (const float4*)rel_emb + tid * 4;
        float4 a0 = __ldg(uu), a1 = __ldg(uu + 1), a2 = __ldg(uu + 2), a3 = __ldg(uu + 3);
        float4 c0 = __ldg(rv), c1 = __ldg(rv + 1), c2 = __ldg(rv + 2), c3 = __ldg(rv + 3);
        float sd = a0.x*c0.x + a0.y*c0.y + a0.z*c0.z + a0.w*c0.w
                 + a1.x*c1.x + a1.y*c1.y + a1.z*c1.z + a1.w*c1.w
                 + a2.x*c2.x + a2.y*c2.y + a2.z*c2.z + a2.w*c2.w
                 + a3.x*c3.x + a3.y*c3.y + a3.z*c3.z + a3.w*c3.w;
        urel_s[tid] = sd * (1.0f / 16.0f);
    }

    // -------- index chain (per warp = one bs) --------
    const float4* E = (const float4*)ent_emb;
    int e0 = __ldg(click_seq + bs);
    int e1 = __ldg(adj_ent + (size_t)e0 * KNB + n);
    int r0 = __ldg(adj_rel + (size_t)e0 * KNB + n);
    int2 e2p = __ldg((const int2*)(adj_ent + (size_t)e1 * KNB) + q);
    int2 r1p = __ldg((const int2*)(adj_rel + (size_t)e1 * KNB) + q);

    float4 e1v = __ldg(E + (size_t)e1 * 4 + q);
    float4 ev0v = make_float4(0.f, 0.f, 0.f, 0.f);
    if (n == 0) ev0v = __ldg(E + (size_t)e0 * 4 + q);

    __syncthreads();   // sync1: urel_s ready

    // -------- p1 softmax (no max-sub: |score| << 1) --------
    float ew0 = __expf(urel_s[r1p.x]);
    float ew1 = __expf(urel_s[r1p.y]);
    float sum = ew0 + ew1;
    sum += __shfl_xor_sync(0xffffffffu, sum, 1);
    sum += __shfl_xor_sync(0xffffffffu, sum, 2);
    float inv = __fdividef(1.f, sum);
    float w0 = ew0 * inv, w1 = ew1 * inv;

    // distribute all 8 (e2, w) across the 4-lane group
    int lb = (tid & 31) & ~3;
    int eA0 = __shfl_sync(0xffffffffu, e2p.x, lb+0), eB0 = __shfl_sync(0xffffffffu, e2p.y, lb+0);
    int eA1 = __shfl_sync(0xffffffffu, e2p.x, lb+1), eB1 = __shfl_sync(0xffffffffu, e2p.y, lb+1);
    int eA2 = __shfl_sync(0xffffffffu, e2p.x, lb+2), eB2 = __shfl_sync(0xffffffffu, e2p.y, lb+2);
    int eA3 = __shfl_sync(0xffffffffu, e2p.x, lb+3), eB3 = __shfl_sync(0xffffffffu, e2p.y, lb+3);
    float wA0 = __shfl_sync(0xffffffffu, w0, lb+0), wB0 = __shfl_sync(0xffffffffu, w1, lb+0);
    float wA1 = __shfl_sync(0xffffffffu, w0, lb+1), wB1 = __shfl_sync(0xffffffffu, w1, lb+1);
    float wA2 = __shfl_sync(0xffffffffu, w0, lb+2), wB2 = __shfl_sync(0xffffffffu, w1, lb+2);
    float wA3 = __shfl_sync(0xffffffffu, w0, lb+3), wB3 = __shfl_sync(0xffffffffu, w1, lb+3);

    // -------- the hot random gather: 8 independent float4 loads --------
    float4 v0 = __ldg(E + (size_t)eA0 * 4 + q);
    float4 v1 = __ldg(E + (size_t)eB0 * 4 + q);
    float4 v2 = __ldg(E + (size_t)eA1 * 4 + q);
    float4 v3 = __ldg(E + (size_t)eB1 * 4 + q);
    float4 v4 = __ldg(E + (size_t)eA2 * 4 + q);
    float4 v5 = __ldg(E + (size_t)eB2 * 4 + q);
    float4 v6 = __ldg(E + (size_t)eA3 * 4 + q);
    float4 v7 = __ldg(E + (size_t)eB3 * 4 + q);

    // -------- p0 softmax (overlaps gather latency) --------
    float p0e = __expf(urel_s[r0]);
    float p0su = p0e;
    p0su += __shfl_xor_sync(0xffffffffu, p0su, 4);
    p0su += __shfl_xor_sync(0xffffffffu, p0su, 8);
    p0su += __shfl_xor_sync(0xffffffffu, p0su, 16);
    float p0w = __fdividef(p0e, p0su);   // p0 for this lane's n
    if (q == 0) p0s[bsl][n] = p0w;

    // -------- t0 = ev0 + sum_n p0[n]*ev1[n][:] via warp reduction --------
    float tx = p0w * e1v.x, ty = p0w * e1v.y, tz = p0w * e1v.z, tw = p0w * e1v.w;
#pragma unroll
    for (int msk = 4; msk <= 16; msk <<= 1) {
        tx += __shfl_xor_sync(0xffffffffu, tx, msk);
        ty += __shfl_xor_sync(0xffffffffu, ty, msk);
        tz += __shfl_xor_sync(0xffffffffu, tz, msk);
        tw += __shfl_xor_sync(0xffffffffu, tw, msk);
    }
    if (n == 0) {
        int qq = q * 4;
        t0s[bsl][qq+0] = ev0v.x + tx;
        t0s[bsl][qq+1] = ev0v.y + ty;
        t0s[bsl][qq+2] = ev0v.z + tz;
        t0s[bsl][qq+3] = ev0v.w + tw;
    }

    // -------- tmp1 accumulate + store --------
    float4 acc;
    acc.x = wA0*v0.x + wB0*v1.x + wA1*v2.x + wB1*v3.x
          + wA2*v4.x + wB2*v5.x + wA3*v6.x + wB3*v7.x;
    acc.y = wA0*v0.y + wB0*v1.y + wA1*v2.y + wB1*v3.y
          + wA2*v4.y + wB2*v5.y + wA3*v6.y + wB3*v7.y;
    acc.z = wA0*v0.z + wB0*v1.z + wA1*v2.z + wB1*v3.z
          + wA2*v4.z + wB2*v5.z + wA3*v6.z + wB3*v7.z;
    acc.w = wA0*v0.w + wB0*v1.w + wA1*v2.w + wB1*v3.w
          + wA2*v4.w + wB2*v5.w + wA3*v6.w + wB3*v7.w;

    {
        int qq = q * 4;
        tmp1s[bsl][n][qq+0] = e1v.x + acc.x;
        tmp1s[bsl][n][qq+1] = e1v.y + acc.y;
        tmp1s[bsl][n][qq+2] = e1v.z + acc.z;
        tmp1s[bsl][n][qq+3] = e1v.w + acc.w;
    }
    __syncthreads();   // sync2: tmp1s, t0s, p0s ready

    // -------- register-resident weight column (shared by ALL matvecs) ------
    int dp = tid & 15;
    float Wcol[16];
#pragma unroll
    for (int d = 0; d < 16; d++) Wcol[d] = Wm[d * 16 + dp];
    float bcol = bbias[dp];

    // -------- hop1 linear + sigmoid: 4 bl per thread --------
    {
        int n2 = tid >> 4;   // 0..7
#pragma unroll
        for (int bl = 0; bl < 4; bl++) {
            float a = bcol;
#pragma unroll
            for (int d = 0; d < 16; d++)
                a = fmaf(tmp1s[bl][n2][d], Wcol[d], a);
            out1s[bl][n2][dp] = fsigmoid(a);
        }
    }
    // -------- o0 (independent of out1s; same phase) --------
    float o0 = 0.f;
    int bl4 = tid >> 4;      // 0..3 for tid<64
    if (tid < 64) {
        float a = bcol;
#pragma unroll
        for (int d2 = 0; d2 < 16; d2++)
            a = fmaf(t0s[bl4][d2], Wcol[d2], a);
        o0 = fsigmoid(a);
    }
    __syncthreads();   // sync3: out1s ready

    if (tid < 64) {
        float tf = o0;
#pragma unroll
        for (int k = 0; k < 8; k++)
            tf = fmaf(p0s[bl4][k], out1s[bl4][k][dp], tf);
        tfs[bl4][dp] = tf;
        __syncwarp(0xffffffffu);
        float a = bcol;
#pragma unroll
        for (int d2 = 0; d2 < 16; d2++)
            a = fmaf(tfs[bl4][d2], Wcol[d2], a);
        g_item[(size_t)(gb * 4 + bl4) * 16 + dp] = fmaxf(tanhf(a), 0.f);
    }

    // -------- last-block-per-batch fusion head (mod-16 counter) --------
    __threadfence();
    __syncthreads();
    if (tid == 0) {
        unsigned int old = atomicAdd(&g_cnt[bq], 1u);
        headflag = ((old & 15u) == 15u);
    }
    __syncthreads();
    if (!headflag) return;

    __shared__ float ps[8][16], pm[8][16], fus[32], hh[64];
    {
        int d = tid & 15, sc = tid >> 4;
        float s = 0.f, mmx = -1e30f;
#pragma unroll
        for (int j = 0; j < 8; j++) {
            float vv = __ldcg(g_item + ((size_t)bq * S + sc * 8 + j) * D + d);
            s += vv;
            mmx = fmaxf(mmx, vv);
        }
        ps[sc][d] = s;
        pm[sc][d] = mmx;
    }
    __syncthreads();
    if (tid < 16) {
        float s = 0.f, mmx = -1e30f;
#pragma unroll
        for (int c = 0; c < 8; c++) { s += ps[c][tid]; mmx = fmaxf(mmx, pm[c][tid]); }
        fus[tid]      = fmaxf(s, 0.f);
        fus[16 + tid] = fmaxf(mmx, 0.f);
    }
    __syncthreads();
    if (tid < 64) {
        float a = __ldg(fc1_b + tid);
#pragma unroll
        for (int i = 0; i < 32; i++)
            a = fmaf(fus[i], __ldg(fc1_W + i * 64 + tid), a);
        hh[tid] = fmaxf(a, 0.f);
    }
    __syncthreads();
    if (tid < 16) {
        float a = __ldg(fc2_b + tid);
#pragma unroll
        for (int i = 0; i < 64; i++)
            a = fmaf(hh[i], __ldg(fc2_W + i * D + tid), a);
        float f = fmaxf(a, 0.f);
        float p = f * __ldg(ent_emb + (size_t)__ldg(v + bq) * D + tid);
        p += __shfl_xor_sync(0xffffu, p, 8);
        p += __shfl_xor_sync(0xffffu, p, 4);
        p += __shfl_xor_sync(0xffffu, p, 2);
        p += __shfl_xor_sync(0xffffu, p, 1);
        if (tid == 0)
            out[bq * (1 + D)] = fsigmoid(p);
    }
}

// ---------------------------------------------------------------------------
extern "C" void kernel_launch(void* const* d_in, const int* in_sizes, int n_in,
                              void* d_out, int out_size)
{
    const float* usr_emb  = (const float*)d_in[0];
    const float* ent_emb  = (const float*)d_in[1];
    const float* rel_emb  = (const float*)d_in[2];
    const float* agg_W    = (const float*)d_in[3];
    const float* agg_b    = (const float*)d_in[4];
    const float* fc1_W    = (const float*)d_in[5];
    const float* fc1_b    = (const float*)d_in[6];
    const float* fc2_W    = (const float*)d_in[7];
    const float* fc2_b    = (const float*)d_in[8];
    const float* mlp_W1   = (const float*)d_in[9];
    const float* mlp_b1   = (const float*)d_in[10];
    const float* mlp_W2   = (const float*)d_in[11];
    const float* mlp_b2   = (const float*)d_in[12];
    const float* mlp_W3   = (const float*)d_in[13];
    const float* mlp_b3   = (const float*)d_in[14];
    const float* mlp_W4   = (const float*)d_in[15];
    const float* mlp_b4   = (const float*)d_in[16];
    const float* se1      = (const float*)d_in[17];
    const float* se2      = (const float*)d_in[18];
    const float* se3      = (const float*)d_in[19];
    const float* noise_e  = (const float*)d_in[20];
    const int*   u        = (const int*)d_in[21];
    const int*   v        = (const int*)d_in[22];
    const int*   click    = (const int*)d_in[23];
    const int*   adj_ent  = (const int*)d_in[24];
    const int*   adj_rel  = (const int*)d_in[25];
    const int*   t        = (const int*)d_in[26];
    float* out = (float*)d_out;

    fused_kernel<<<NDIFF + NGATH, 128>>>(ent_emb, rel_emb, agg_W, agg_b, usr_emb,
                                         mlp_W1, mlp_b1, mlp_W2, mlp_b2,
                                         mlp_W3, mlp_b3, mlp_W4, mlp_b4,
                                         se1, se2, se3, noise_e,
                                         fc1_W, fc1_b, fc2_W, fc2_b,
                                         u, v, t, click, adj_ent, adj_rel, out);
}

// round 13
// speedup vs baseline: 1.5717x; 1.0357x over previous
#include <cuda_runtime.h>
#include <cuda_bf16.h>
#include <math.h>

#define B 512
#define S 64
#define KNB 8
#define D 16
#define NSTEPS 100
#define NUNITS 128

#define BS    (B*S)       // 32768
#define NDIFF (B)         // 512 diffusion blocks (1 batch each)
#define NGATH (BS/4)      // 8192 gather blocks (4 (b,s) each)

// ---- device scratch (static, allocation-free) ----
__device__ float g_item[BS * D];
__device__ unsigned int g_cnt[B];   // monotonic; head = (old & 15) == 15

__device__ __forceinline__ float fsigmoid(float a) {
    return __fdividef(1.f, 1.f + __expf(-a));
}

// ---------------------------------------------------------------------------
// Single fused kernel, 128-thread blocks, 14 blocks/SM target.
// ---------------------------------------------------------------------------
__global__ __launch_bounds__(128, 14) void fused_kernel(
    const float* __restrict__ ent_emb,
    const float* __restrict__ rel_emb,
    const float* __restrict__ agg_W, const float* __restrict__ agg_b,
    const float* __restrict__ usr_emb,
    const float* __restrict__ W1, const float* __restrict__ b1,
    const float* __restrict__ W2, const float* __restrict__ b2,
    const float* __restrict__ W3, const float* __restrict__ b3,
    const float* __restrict__ W4, const float* __restrict__ b4,
    const float* __restrict__ se1, const float* __restrict__ se2,
    const float* __restrict__ se3,
    const float* __restrict__ noise_e,
    const float* __restrict__ fc1_W, const float* __restrict__ fc1_b,
    const float* __restrict__ fc2_W, const float* __restrict__ fc2_b,
    const int* __restrict__ u, const int* __restrict__ v,
    const int* __restrict__ t,
    const int* __restrict__ click_seq,
    const int* __restrict__ adj_ent, const int* __restrict__ adj_rel,
    float* __restrict__ out)
{
    int tid = threadIdx.x;

    // ======================= diffusion path =======================
    if (blockIdx.x < NDIFF) {
        __shared__ float red[128];
        __shared__ float xs[16], ha[128], hb[128], p4[8][16];
        int b = blockIdx.x;
        int tb = __ldg(t + b);

        float lg = 0.f;
        if (tid < NSTEPS && tid <= tb) {
            float z = -6.f + 12.f * (float)tid / 99.f;
            float beta = fsigmoid(z) * (0.005f - 1e-5f) + 1e-5f;
            lg = log1pf(-beta);
        }
        red[tid] = lg;
        __syncthreads();
#pragma unroll
        for (int st = 64; st > 0; st >>= 1) {
            if (tid < st) red[tid] += red[tid + st];
            __syncthreads();
        }
        float ap  = __expf(red[0]);
        float ab  = sqrtf(ap);
        float omb = sqrtf(1.f - ap);

        if (tid < 16)
            xs[tid] = __ldg(usr_emb + (size_t)__ldg(u + b) * D + tid) * ab
                    + __ldg(noise_e + b * D + tid) * omb;
        __syncthreads();
        {
            float a = __ldg(b1 + tid) + __ldg(se1 + tb * NUNITS + tid);
#pragma unroll
            for (int d = 0; d < 16; d++)
                a = fmaf(xs[d], __ldg(W1 + d * NUNITS + tid), a);
            ha[tid] = fmaxf(a, 0.f);
        }
        __syncthreads();
        {
            float a0 = 0.f, a1 = 0.f;
#pragma unroll
            for (int i = 0; i < 128; i += 2) {
                a0 = fmaf(ha[i+0], __ldg(W2 + (i+0) * NUNITS + tid), a0);
                a1 = fmaf(ha[i+1], __ldg(W2 + (i+1) * NUNITS + tid), a1);
            }
            float a = __ldg(b2 + tid) + __ldg(se2 + tb * NUNITS + tid) + a0 + a1;
            hb[tid] = fmaxf(a, 0.f);
        }
        __syncthreads();
        {
            float a0 = 0.f, a1 = 0.f;
#pragma unroll
            for (int i = 0; i < 128; i += 2) {
                a0 = fmaf(hb[i+0], __ldg(W3 + (i+0) * NUNITS + tid), a0);
                a1 = fmaf(hb[i+1], __ldg(W3 + (i+1) * NUNITS + tid), a1);
            }
            float a = __ldg(b3 + tid) + __ldg(se3 + tb * NUNITS + tid) + a0 + a1;
            ha[tid] = fmaxf(a, 0.f);
        }
        __syncthreads();
        {
            int g = tid >> 4, d = tid & 15;
            float a = 0.f;
#pragma unroll
            for (int i = 0; i < 16; i++)
                a = fmaf(ha[g * 16 + i], __ldg(W4 + (g * 16 + i) * D + d), a);
            p4[g][d] = a;
        }
        __syncthreads();
        if (tid < 16) {
            float a = __ldg(b4 + tid);
#pragma unroll
            for (int g = 0; g < 8; g++) a += p4[g][tid];
            out[b * (1 + D) + 1 + tid] = a;
        }
        return;
    }

    // ======================= gather path =======================
    __shared__ float urel_s[64];
    __shared__ float Wm[256], bbias[16];
    __shared__ float tmp1s[4][8][20];
    __shared__ float out1s[4][8][18];
    __shared__ float p0s[4][8];
    __shared__ float t0s[4][20];
    __shared__ float tfs[4][17];
    __shared__ int   headflag;

    int gb  = blockIdx.x - NDIFF;
    int bsl = tid >> 5, n = (tid >> 2) & 7, q = tid & 3;
    int bs  = gb * 4 + bsl;
    int bq  = bs >> 6;

    Wm[tid]       = __ldg(agg_W + tid);
    Wm[tid + 128] = __ldg(agg_W + tid + 128);
    if (tid < 16) bbias[tid] = __ldg(agg_b + tid);

    // per-block urel table
    if (tid < 64) {
        const float4* uu = (const float4*)usr_emb + (size_t)__ldg(u + bq) * 4;
        const float4* rv = (const float4*)rel_emb + tid * 4;
        float4 a0 = __ldg(uu), a1 = __ldg(uu + 1), a2 = __ldg(uu + 2), a3 = __ldg(uu + 3);
        float4 c0 = __ldg(rv), c1 = __ldg(rv + 1), c2 = __ldg(rv + 2), c3 = __ldg(rv + 3);
        float sd = a0.x*c0.x + a0.y*c0.y + a0.z*c0.z + a0.w*c0.w
                 + a1.x*c1.x + a1.y*c1.y + a1.z*c1.z + a1.w*c1.w
                 + a2.x*c2.x + a2.y*c2.y + a2.z*c2.z + a2.w*c2.w
                 + a3.x*c3.x + a3.y*c3.y + a3.z*c3.z + a3.w*c3.w;
        urel_s[tid] = sd * (1.0f / 16.0f);
    }

    // -------- index chain (per warp = one bs) --------
    const float4* E = (const float4*)ent_emb;
    int e0 = __ldg(click_seq + bs);
    int e1 = __ldg(adj_ent + (size_t)e0 * KNB + n);
    int r0 = __ldg(adj_rel + (size_t)e0 * KNB + n);
    int2 e2p = __ldg((const int2*)(adj_ent + (size_t)e1 * KNB) + q);
    int2 r1p = __ldg((const int2*)(adj_rel + (size_t)e1 * KNB) + q);

    float4 e1v = __ldg(E + (size_t)e1 * 4 + q);
    float4 ev0v = make_float4(0.f, 0.f, 0.f, 0.f);
    if (n == 0) ev0v = __ldg(E + (size_t)e0 * 4 + q);

    __syncthreads();   // sync1: urel_s ready

    // -------- p1 softmax (no max-sub: |score| << 1) --------
    float ew0 = __expf(urel_s[r1p.x]);
    float ew1 = __expf(urel_s[r1p.y]);
    float sum = ew0 + ew1;
    sum += __shfl_xor_sync(0xffffffffu, sum, 1);
    sum += __shfl_xor_sync(0xffffffffu, sum, 2);
    float inv = __fdividef(1.f, sum);
    float w0 = ew0 * inv, w1 = ew1 * inv;

    // distribute all 8 (e2, w) across the 4-lane group
    int lb = (tid & 31) & ~3;
    int eA0 = __shfl_sync(0xffffffffu, e2p.x, lb+0), eB0 = __shfl_sync(0xffffffffu, e2p.y, lb+0);
    int eA1 = __shfl_sync(0xffffffffu, e2p.x, lb+1), eB1 = __shfl_sync(0xffffffffu, e2p.y, lb+1);
    int eA2 = __shfl_sync(0xffffffffu, e2p.x, lb+2), eB2 = __shfl_sync(0xffffffffu, e2p.y, lb+2);
    int eA3 = __shfl_sync(0xffffffffu, e2p.x, lb+3), eB3 = __shfl_sync(0xffffffffu, e2p.y, lb+3);
    float wA0 = __shfl_sync(0xffffffffu, w0, lb+0), wB0 = __shfl_sync(0xffffffffu, w1, lb+0);
    float wA1 = __shfl_sync(0xffffffffu, w0, lb+1), wB1 = __shfl_sync(0xffffffffu, w1, lb+1);
    float wA2 = __shfl_sync(0xffffffffu, w0, lb+2), wB2 = __shfl_sync(0xffffffffu, w1, lb+2);
    float wA3 = __shfl_sync(0xffffffffu, w0, lb+3), wB3 = __shfl_sync(0xffffffffu, w1, lb+3);

    // -------- gather wave 1 (4 independent float4 loads) --------
    float4 v0 = __ldg(E + (size_t)eA0 * 4 + q);
    float4 v1 = __ldg(E + (size_t)eB0 * 4 + q);
    float4 v2 = __ldg(E + (size_t)eA1 * 4 + q);
    float4 v3 = __ldg(E + (size_t)eB1 * 4 + q);

    // -------- p0 softmax + t0 reduction (ALU work under wave-1 latency) ----
    float p0e = __expf(urel_s[r0]);
    float p0su = p0e;
    p0su += __shfl_xor_sync(0xffffffffu, p0su, 4);
    p0su += __shfl_xor_sync(0xffffffffu, p0su, 8);
    p0su += __shfl_xor_sync(0xffffffffu, p0su, 16);
    float p0w = __fdividef(p0e, p0su);
    if (q == 0) p0s[bsl][n] = p0w;

    float tx = p0w * e1v.x, ty = p0w * e1v.y, tz = p0w * e1v.z, tw = p0w * e1v.w;
#pragma unroll
    for (int msk = 4; msk <= 16; msk <<= 1) {
        tx += __shfl_xor_sync(0xffffffffu, tx, msk);
        ty += __shfl_xor_sync(0xffffffffu, ty, msk);
        tz += __shfl_xor_sync(0xffffffffu, tz, msk);
        tw += __shfl_xor_sync(0xffffffffu, tw, msk);
    }
    if (n == 0) {
        int qq = q * 4;
        t0s[bsl][qq+0] = ev0v.x + tx;
        t0s[bsl][qq+1] = ev0v.y + ty;
        t0s[bsl][qq+2] = ev0v.z + tz;
        t0s[bsl][qq+3] = ev0v.w + tw;
    }

    // -------- consume wave 1 --------
    float accx = wA0*v0.x + wB0*v1.x + wA1*v2.x + wB1*v3.x;
    float accy = wA0*v0.y + wB0*v1.y + wA1*v2.y + wB1*v3.y;
    float accz = wA0*v0.z + wB0*v1.z + wA1*v2.z + wB1*v3.z;
    float accw = wA0*v0.w + wB0*v1.w + wA1*v2.w + wB1*v3.w;

    // -------- gather wave 2 --------
    float4 v4 = __ldg(E + (size_t)eA2 * 4 + q);
    float4 v5 = __ldg(E + (size_t)eB2 * 4 + q);
    float4 v6 = __ldg(E + (size_t)eA3 * 4 + q);
    float4 v7 = __ldg(E + (size_t)eB3 * 4 + q);

    accx += wA2*v4.x + wB2*v5.x + wA3*v6.x + wB3*v7.x;
    accy += wA2*v4.y + wB2*v5.y + wA3*v6.y + wB3*v7.y;
    accz += wA2*v4.z + wB2*v5.z + wA3*v6.z + wB3*v7.z;
    accw += wA2*v4.w + wB2*v5.w + wA3*v6.w + wB3*v7.w;

    {
        int qq = q * 4;
        tmp1s[bsl][n][qq+0] = e1v.x + accx;
        tmp1s[bsl][n][qq+1] = e1v.y + accy;
        tmp1s[bsl][n][qq+2] = e1v.z + accz;
        tmp1s[bsl][n][qq+3] = e1v.w + accw;
    }
    __syncthreads();   // sync2: tmp1s, t0s, p0s ready

    // -------- register-resident weight column --------
    int dp = tid & 15;
    float Wcol[16];
#pragma unroll
    for (int d = 0; d < 16; d++) Wcol[d] = Wm[d * 16 + dp];
    float bcol = bbias[dp];

    // -------- hop1 linear + sigmoid: 4 bl per thread --------
    {
        int n2 = tid >> 4;
#pragma unroll
        for (int bl = 0; bl < 4; bl++) {
            float a = bcol;
#pragma unroll
            for (int d = 0; d < 16; d++)
                a = fmaf(tmp1s[bl][n2][d], Wcol[d], a);
            out1s[bl][n2][dp] = fsigmoid(a);
        }
    }
    // -------- o0 (independent; same phase) --------
    float o0 = 0.f;
    int bl4 = tid >> 4;
    if (tid < 64) {
        float a = bcol;
#pragma unroll
        for (int d2 = 0; d2 < 16; d2++)
            a = fmaf(t0s[bl4][d2], Wcol[d2], a);
        o0 = fsigmoid(a);
    }
    __syncthreads();   // sync3: out1s ready

    if (tid < 64) {
        float tf = o0;
#pragma unroll
        for (int k = 0; k < 8; k++)
            tf = fmaf(p0s[bl4][k], out1s[bl4][k][dp], tf);
        tfs[bl4][dp] = tf;
        __syncwarp(0xffffffffu);
        float a = bcol;
#pragma unroll
        for (int d2 = 0; d2 < 16; d2++)
            a = fmaf(tfs[bl4][d2], Wcol[d2], a);
        g_item[(size_t)(gb * 4 + bl4) * 16 + dp] = fmaxf(tanhf(a), 0.f);
    }

    // -------- last-block-per-batch fusion head (mod-16 counter) --------
    __threadfence();
    __syncthreads();
    if (tid == 0) {
        unsigned int old = atomicAdd(&g_cnt[bq], 1u);
        headflag = ((old & 15u) == 15u);
    }
    __syncthreads();
    if (!headflag) return;

    __shared__ float ps[8][16], pm[8][16], fus[32], hh[64];
    {
        int d = tid & 15, sc = tid >> 4;
        float s = 0.f, mmx = -1e30f;
#pragma unroll
        for (int j = 0; j < 8; j++) {
            float vv = __ldcg(g_item + ((size_t)bq * S + sc * 8 + j) * D + d);
            s += vv;
            mmx = fmaxf(mmx, vv);
        }
        ps[sc][d] = s;
        pm[sc][d] = mmx;
    }
    __syncthreads();
    if (tid < 16) {
        float s = 0.f, mmx = -1e30f;
#pragma unroll
        for (int c = 0; c < 8; c++) { s += ps[c][tid]; mmx = fmaxf(mmx, pm[c][tid]); }
        fus[tid]      = fmaxf(s, 0.f);
        fus[16 + tid] = fmaxf(mmx, 0.f);
    }
    __syncthreads();
    if (tid < 64) {
        float a = __ldg(fc1_b + tid);
#pragma unroll
        for (int i = 0; i < 32; i++)
            a = fmaf(fus[i], __ldg(fc1_W + i * 64 + tid), a);
        hh[tid] = fmaxf(a, 0.f);
    }
    __syncthreads();
    if (tid < 16) {
        float a = __ldg(fc2_b + tid);
#pragma unroll
        for (int i = 0; i < 64; i++)
            a = fmaf(hh[i], __ldg(fc2_W + i * D + tid), a);
        float f = fmaxf(a, 0.f);
        float p = f * __ldg(ent_emb + (size_t)__ldg(v + bq) * D + tid);
        p += __shfl_xor_sync(0xffffu, p, 8);
        p += __shfl_xor_sync(0xffffu, p, 4);
        p += __shfl_xor_sync(0xffffu, p, 2);
        p += __shfl_xor_sync(0xffffu, p, 1);
        if (tid == 0)
            out[bq * (1 + D)] = fsigmoid(p);
    }
}

// ---------------------------------------------------------------------------
extern "C" void kernel_launch(void* const* d_in, const int* in_sizes, int n_in,
                              void* d_out, int out_size)
{
    const float* usr_emb  = (const float*)d_in[0];
    const float* ent_emb  = (const float*)d_in[1];
    const float* rel_emb  = (const float*)d_in[2];
    const float* agg_W    = (const float*)d_in[3];
    const float* agg_b    = (const float*)d_in[4];
    const float* fc1_W    = (const float*)d_in[5];
    const float* fc1_b    = (const float*)d_in[6];
    const float* fc2_W    = (const float*)d_in[7];
    const float* fc2_b    = (const float*)d_in[8];
    const float* mlp_W1   = (const float*)d_in[9];
    const float* mlp_b1   = (const float*)d_in[10];
    const float* mlp_W2   = (const float*)d_in[11];
    const float* mlp_b2   = (const float*)d_in[12];
    const float* mlp_W3   = (const float*)d_in[13];
    const float* mlp_b3   = (const float*)d_in[14];
    const float* mlp_W4   = (const float*)d_in[15];
    const float* mlp_b4   = (const float*)d_in[16];
    const float* se1      = (const float*)d_in[17];
    const float* se2      = (const float*)d_in[18];
    const float* se3      = (const float*)d_in[19];
    const float* noise_e  = (const float*)d_in[20];
    const int*   u        = (const int*)d_in[21];
    const int*   v        = (const int*)d_in[22];
    const int*   click    = (const int*)d_in[23];
    const int*   adj_ent  = (const int*)d_in[24];
    const int*   adj_rel  = (const int*)d_in[25];
    const int*   t        = (const int*)d_in[26];
    float* out = (float*)d_out;

    fused_kernel<<<NDIFF + NGATH, 128>>>(ent_emb, rel_emb, agg_W, agg_b, usr_emb,
                                         mlp_W1, mlp_b1, mlp_W2, mlp_b2,
                                         mlp_W3, mlp_b3, mlp_W4, mlp_b4,
                                         se1, se2, se3, noise_e,
                                         fc1_W, fc1_b, fc2_W, fc2_b,
                                         u, v, t, click, adj_ent, adj_rel, out);
}